// round 2
// baseline (speedup 1.0000x reference)
#include <cuda_runtime.h>
#include <math.h>

#define HH 48
#define WW 48
#define SP 2304          // 48*48
#define CC 192
#define BB 8
#define TOTAL 3538944    // 8*192*2304

// ---------------- scratch (no allocations allowed) ----------------
__device__ float g_act[TOTAL];      // swish(gn(.)) activations (reused)
__device__ float g_h[TOTAL];        // after conv1+affine
__device__ float g_xres[TOTAL];     // residual output of resnet block
__device__ float g_q[BB*16*SP];
__device__ float g_kv[BB*32*SP];
__device__ float g_attnout[BB*16*SP];
__device__ float g_mean[BB*32];
__device__ float g_rstd[BB*32];
__device__ float g_gbsum[BB*CC];

// ---------------- helpers ----------------
__device__ __forceinline__ float warp_red(float v) {
    #pragma unroll
    for (int o = 16; o > 0; o >>= 1) v += __shfl_down_sync(0xffffffffu, v, o);
    return v;
}

// ---------------- FeatureWiseAffine: gb_sum[b][c] ----------------
__global__ void affine_kernel(const float* __restrict__ temb,
                              const float* __restrict__ aw,   // [384][192]
                              const float* __restrict__ ab,   // [384]
                              float* __restrict__ gbsum) {
    int b = blockIdx.x;
    int c = threadIdx.x;   // 192
    __shared__ float t[192];
    t[c] = temb[b * 192 + c];
    __syncthreads();
    float s = ab[c] + ab[192 + c];
    const float* w1 = aw + c * 192;
    const float* w2 = aw + (192 + c) * 192;
    for (int e = 0; e < 192; ++e) s = fmaf(t[e], w1[e] + w2[e], s);
    gbsum[b * 192 + c] = 0.5f * s;
}

// ---------------- GroupNorm stats: one block per (b,group) ----------------
__global__ __launch_bounds__(256) void gn_stats(const float* __restrict__ in,
                                                float* __restrict__ mean,
                                                float* __restrict__ rstd) {
    int bg = blockIdx.x;                 // 0..255 ; group region is contiguous
    const float* base = in + (long)bg * 13824;   // 6 ch * 2304
    float s = 0.f, s2 = 0.f;
    for (int i = threadIdx.x; i < 13824; i += 256) {
        float v = base[i];
        s += v; s2 = fmaf(v, v, s2);
    }
    __shared__ float shs[8], shs2[8];
    int w = threadIdx.x >> 5, l = threadIdx.x & 31;
    s = warp_red(s); s2 = warp_red(s2);
    if (l == 0) { shs[w] = s; shs2[w] = s2; }
    __syncthreads();
    if (w == 0) {
        s  = (l < 8) ? shs[l]  : 0.f;
        s2 = (l < 8) ? shs2[l] : 0.f;
        s = warp_red(s); s2 = warp_red(s2);
        if (l == 0) {
            float m = s * (1.f / 13824.f);
            float var = s2 * (1.f / 13824.f) - m * m;
            mean[bg] = m;
            rstd[bg] = rsqrtf(var + 1e-5f);
        }
    }
}

// ---------------- GroupNorm apply + swish ----------------
__global__ __launch_bounds__(256) void gn_apply(const float* __restrict__ in,
                                                const float* __restrict__ mean,
                                                const float* __restrict__ rstd,
                                                const float* __restrict__ w,
                                                const float* __restrict__ bb,
                                                float* __restrict__ out) {
    int idx = blockIdx.x * 256 + threadIdx.x;      // exact grid
    int bc = idx / SP;
    int b = bc / CC;
    int c = bc - b * CC;
    int sidx = b * 32 + c / 6;
    float y = (in[idx] - mean[sidx]) * rstd[sidx] * w[c] + bb[c];
    out[idx] = y / (1.f + __expf(-y));
}

// ---------------- 3x3 conv (pad=1), OC=192, epilogue selectable ----------------
// EPI 0: affine  y = y + gs*y + gs  (extra = gb_sum [B*192])
// EPI 1: add     y = y + extra[idx] (extra = full tensor)
template<int CIN, int EPI>
__global__ __launch_bounds__(256) void conv3x3(const float* __restrict__ in,
                                               const float* __restrict__ wgt,
                                               const float* __restrict__ bias,
                                               const float* __restrict__ extra,
                                               float* __restrict__ out) {
    const int octile = blockIdx.x;     // 6 tiles of 32 oc
    const int y0 = blockIdx.y * 8;     // 6 row tiles of 8 rows
    const int b = blockIdx.z;
    const int tid = threadIdx.x;
    const int lane = tid & 63;         // 64 spatial lanes
    const int g = tid >> 6;            // 4 oc groups of 8

    __shared__ float s_in[8 * 10 * 50];   // 8 ci x 10 rows x 50 cols
    __shared__ float s_w[32 * 8 * 9];     // 32 oc x 8 ci x 9 taps

    float acc[8][6];
    #pragma unroll
    for (int o = 0; o < 8; ++o)
        #pragma unroll
        for (int k = 0; k < 6; ++k) acc[o][k] = 0.f;

    int prow[6], pcol[6];
    #pragma unroll
    for (int k = 0; k < 6; ++k) {
        int p = lane + 64 * k;        // 0..383 -> 8 rows x 48 cols
        prow[k] = p / 48;
        pcol[k] = p - prow[k] * 48;
    }

    const int nchunks = CIN / 8;
    for (int ch = 0; ch < nchunks; ++ch) {
        const int ci0 = ch * 8;
        __syncthreads();
        // stage input halo tile: rows y0-1..y0+8, cols -1..48
        for (int i = tid; i < 4000; i += 256) {
            int ci = i / 500;
            int rem = i - ci * 500;
            int r = rem / 50;
            int cc2 = rem - r * 50;
            int gy = y0 - 1 + r;
            int gx = cc2 - 1;
            float v = 0.f;
            if (gy >= 0 && gy < HH && (unsigned)gx < (unsigned)WW)
                v = in[(((long)b * CIN + ci0 + ci) * HH + gy) * WW + gx];
            s_in[i] = v;
        }
        // stage weights: 32 oc x 8 ci x 9 taps (contiguous per oc)
        for (int i = tid; i < 2304; i += 256) {
            int o = i / 72;
            int r = i - o * 72;
            s_w[i] = wgt[(((long)(octile * 32 + o) * CIN + ci0) * 9) + r];
        }
        __syncthreads();

        for (int ci = 0; ci < 8; ++ci) {
            const float* wbase = &s_w[(g * 8) * 72 + ci * 9];
            const float* ibase = &s_in[ci * 500];
            #pragma unroll
            for (int dy = 0; dy < 3; ++dy) {
                #pragma unroll
                for (int dx = 0; dx < 3; ++dx) {
                    float wv[8];
                    #pragma unroll
                    for (int o = 0; o < 8; ++o) wv[o] = wbase[o * 72 + dy * 3 + dx];
                    #pragma unroll
                    for (int k = 0; k < 6; ++k) {
                        float iv = ibase[(prow[k] + dy) * 50 + pcol[k] + dx];
                        #pragma unroll
                        for (int o = 0; o < 8; ++o)
                            acc[o][k] = fmaf(wv[o], iv, acc[o][k]);
                    }
                }
            }
        }
    }

    #pragma unroll
    for (int o = 0; o < 8; ++o) {
        int oc = octile * 32 + g * 8 + o;
        float bv = bias[oc];
        float gs = (EPI == 0) ? extra[b * CC + oc] : 0.f;
        #pragma unroll
        for (int k = 0; k < 6; ++k) {
            int idx = (((long)b * CC + oc) * HH + (y0 + prow[k])) * WW + pcol[k];
            float y = acc[o][k] + bv;
            if (EPI == 0) y = y + gs * y + gs;
            else          y = y + extra[idx];
            out[idx] = y;
        }
    }
}

// ---------------- 1x1 conv (GEMM over channels), no bias ----------------
template<int CO>
__global__ __launch_bounds__(256) void conv1x1(const float* __restrict__ in,
                                               const float* __restrict__ wgt,
                                               float* __restrict__ out) {
    const int b = blockIdx.y;
    const int p0 = blockIdx.x * 256;
    const int tid = threadIdx.x;
    __shared__ float s_w[CO * 192];
    __shared__ float s_x[16 * 256];
    for (int i = tid; i < CO * 192; i += 256) s_w[i] = wgt[i];
    float acc[CO];
    #pragma unroll
    for (int co = 0; co < CO; ++co) acc[co] = 0.f;

    for (int c0 = 0; c0 < 192; c0 += 16) {
        __syncthreads();
        for (int i = tid; i < 16 * 256; i += 256) {
            int ci = i >> 8;
            int pp = i & 255;
            s_x[i] = in[((long)b * 192 + c0 + ci) * SP + p0 + pp];
        }
        __syncthreads();
        for (int ci = 0; ci < 16; ++ci) {
            float xv = s_x[ci * 256 + tid];
            #pragma unroll
            for (int co = 0; co < CO; ++co)
                acc[co] = fmaf(s_w[co * 192 + c0 + ci], xv, acc[co]);
        }
    }
    #pragma unroll
    for (int co = 0; co < CO; ++co)
        out[((long)b * CO + co) * SP + p0 + tid] = acc[co];
}

// ---------------- cross-attention, flash-style, 1 thread per query ----------------
// q: [B][16][2304]; kv: [B][32][2304] (k = ch 0..15, v = ch 16..31)
// out[b][c][p] = (softmax_j(0.25 * q_p . k_j) V)_c
__global__ __launch_bounds__(128) void attn_kernel(const float* __restrict__ q,
                                                   const float* __restrict__ kv,
                                                   float* __restrict__ out) {
    const int b = blockIdx.y;
    const int q0 = blockIdx.x * 128;
    const int tid = threadIdx.x;

    __shared__ float q_s[16 * 128];
    __shared__ float k_s[16 * 128];
    __shared__ float v_s[16 * 128];

    for (int i = tid; i < 16 * 128; i += 128) {
        int c = i >> 7;
        int p = i & 127;
        q_s[i] = q[((long)b * 16 + c) * SP + q0 + p];
    }
    __syncthreads();
    float qr[16];
    #pragma unroll
    for (int c = 0; c < 16; ++c) qr[c] = q_s[c * 128 + tid];

    float m = -3.4e38f, l = 0.f;
    float acc[16];
    #pragma unroll
    for (int c = 0; c < 16; ++c) acc[c] = 0.f;

    for (int kc0 = 0; kc0 < SP; kc0 += 128) {
        __syncthreads();
        for (int i = tid; i < 16 * 128; i += 128) {
            int c = i >> 7;
            int p = i & 127;
            k_s[i] = kv[((long)b * 32 + c) * SP + kc0 + p];
            v_s[i] = kv[((long)b * 32 + 16 + c) * SP + kc0 + p];
        }
        __syncthreads();
        #pragma unroll 2
        for (int j = 0; j < 128; ++j) {
            float s = 0.f;
            #pragma unroll
            for (int c = 0; c < 16; ++c) s = fmaf(qr[c], k_s[c * 128 + j], s);
            s *= 0.25f;
            if (s > m) {
                float corr = __expf(m - s);
                m = s;
                l *= corr;
                #pragma unroll
                for (int c = 0; c < 16; ++c) acc[c] *= corr;
            }
            float p = __expf(s - m);
            l += p;
            #pragma unroll
            for (int c = 0; c < 16; ++c) acc[c] = fmaf(p, v_s[c * 128 + j], acc[c]);
        }
    }
    float inv = 1.f / l;
    #pragma unroll
    for (int c = 0; c < 16; ++c)
        out[((long)b * 16 + c) * SP + q0 + tid] = acc[c] * inv;
}

// ---------------- launcher ----------------
extern "C" void kernel_launch(void* const* d_in, const int* in_sizes, int n_in,
                              void* d_out, int out_size) {
    const float* x       = (const float*)d_in[0];
    const float* xe      = (const float*)d_in[1];
    const float* temb    = (const float*)d_in[2];
    const float* gn1_w   = (const float*)d_in[3];
    const float* gn1_b   = (const float*)d_in[4];
    const float* conv1_w = (const float*)d_in[5];
    const float* conv1_b = (const float*)d_in[6];
    const float* aff_w   = (const float*)d_in[7];
    const float* aff_b   = (const float*)d_in[8];
    const float* gn2_w   = (const float*)d_in[9];
    const float* gn2_b   = (const float*)d_in[10];
    const float* conv2_w = (const float*)d_in[11];
    const float* conv2_b = (const float*)d_in[12];
    const float* q_w     = (const float*)d_in[13];
    const float* kv_w    = (const float*)d_in[14];
    const float* out_w   = (const float*)d_in[15];
    const float* out_b   = (const float*)d_in[16];

    float *act, *h, *xres, *qb, *kvb, *attno, *mean, *rstd, *gbsum;
    cudaGetSymbolAddress((void**)&act,   g_act);
    cudaGetSymbolAddress((void**)&h,     g_h);
    cudaGetSymbolAddress((void**)&xres,  g_xres);
    cudaGetSymbolAddress((void**)&qb,    g_q);
    cudaGetSymbolAddress((void**)&kvb,   g_kv);
    cudaGetSymbolAddress((void**)&attno, g_attnout);
    cudaGetSymbolAddress((void**)&mean,  g_mean);
    cudaGetSymbolAddress((void**)&rstd,  g_rstd);
    cudaGetSymbolAddress((void**)&gbsum, g_gbsum);

    // FeatureWiseAffine coefficients (tiny)
    affine_kernel<<<BB, 192>>>(temb, aff_w, aff_b, gbsum);

    // ResnetBlock
    gn_stats<<<BB * 32, 256>>>(x, mean, rstd);
    gn_apply<<<TOTAL / 256, 256>>>(x, mean, rstd, gn1_w, gn1_b, act);
    conv3x3<192, 0><<<dim3(6, 6, BB), 256>>>(act, conv1_w, conv1_b, gbsum, h);
    gn_stats<<<BB * 32, 256>>>(h, mean, rstd);
    gn_apply<<<TOTAL / 256, 256>>>(h, mean, rstd, gn2_w, gn2_b, act);
    conv3x3<192, 1><<<dim3(6, 6, BB), 256>>>(act, conv2_w, conv2_b, x, xres);

    // CrossAttention
    conv1x1<16><<<dim3(9, BB), 256>>>(xres, q_w, qb);
    conv1x1<32><<<dim3(9, BB), 256>>>(xe, kv_w, kvb);
    attn_kernel<<<dim3(18, BB), 128>>>(qb, kvb, attno);
    conv3x3<16, 1><<<dim3(6, 6, BB), 256>>>(attno, out_w, out_b, xres, (float*)d_out);
}

// round 3
// speedup vs baseline: 1.2122x; 1.2122x over previous
#include <cuda_runtime.h>
#include <math.h>

#define HH 48
#define WW 48
#define SP 2304          // 48*48
#define CC 192
#define BB 8
#define TOTAL 3538944    // 8*192*2304

typedef unsigned long long u64;

// ---------------- scratch (no allocations allowed) ----------------
__device__ float g_act[TOTAL];
__device__ float g_h[TOTAL];
__device__ float g_xres[TOTAL];
__device__ float g_q[BB*16*SP];
__device__ float g_kv[BB*32*SP];
__device__ float g_attnout[BB*16*SP];
__device__ float g_mean[BB*32];
__device__ float g_rstd[BB*32];
__device__ float g_gbsum[BB*CC];

// ---------------- f32x2 helpers ----------------
__device__ __forceinline__ u64 pack2(float lo, float hi) {
    u64 r; asm("mov.b64 %0, {%1, %2};" : "=l"(r) : "f"(lo), "f"(hi)); return r;
}
__device__ __forceinline__ void unpack2(u64 v, float& lo, float& hi) {
    asm("mov.b64 {%0, %1}, %2;" : "=f"(lo), "=f"(hi) : "l"(v));
}
__device__ __forceinline__ u64 fma2(u64 a, u64 b, u64 c) {
    u64 d; asm("fma.rn.f32x2 %0, %1, %2, %3;" : "=l"(d) : "l"(a), "l"(b), "l"(c)); return d;
}

__device__ __forceinline__ float warp_red(float v) {
    #pragma unroll
    for (int o = 16; o > 0; o >>= 1) v += __shfl_down_sync(0xffffffffu, v, o);
    return v;
}

// ---------------- FeatureWiseAffine: gb_sum[b][c] ----------------
__global__ void affine_kernel(const float* __restrict__ temb,
                              const float* __restrict__ aw,
                              const float* __restrict__ ab,
                              float* __restrict__ gbsum) {
    int b = blockIdx.x;
    int c = threadIdx.x;
    __shared__ float t[192];
    t[c] = temb[b * 192 + c];
    __syncthreads();
    float s = ab[c] + ab[192 + c];
    const float* w1 = aw + c * 192;
    const float* w2 = aw + (192 + c) * 192;
    for (int e = 0; e < 192; ++e) s = fmaf(t[e], w1[e] + w2[e], s);
    gbsum[b * 192 + c] = 0.5f * s;
}

// ---------------- GroupNorm stats ----------------
__global__ __launch_bounds__(256) void gn_stats(const float* __restrict__ in,
                                                float* __restrict__ mean,
                                                float* __restrict__ rstd) {
    int bg = blockIdx.x;
    const float* base = in + (long)bg * 13824;
    float s = 0.f, s2 = 0.f;
    for (int i = threadIdx.x; i < 13824; i += 256) {
        float v = base[i];
        s += v; s2 = fmaf(v, v, s2);
    }
    __shared__ float shs[8], shs2[8];
    int w = threadIdx.x >> 5, l = threadIdx.x & 31;
    s = warp_red(s); s2 = warp_red(s2);
    if (l == 0) { shs[w] = s; shs2[w] = s2; }
    __syncthreads();
    if (w == 0) {
        s  = (l < 8) ? shs[l]  : 0.f;
        s2 = (l < 8) ? shs2[l] : 0.f;
        s = warp_red(s); s2 = warp_red(s2);
        if (l == 0) {
            float m = s * (1.f / 13824.f);
            float var = s2 * (1.f / 13824.f) - m * m;
            mean[bg] = m;
            rstd[bg] = rsqrtf(var + 1e-5f);
        }
    }
}

// ---------------- GroupNorm apply + swish ----------------
__global__ __launch_bounds__(256) void gn_apply(const float* __restrict__ in,
                                                const float* __restrict__ mean,
                                                const float* __restrict__ rstd,
                                                const float* __restrict__ w,
                                                const float* __restrict__ bb,
                                                float* __restrict__ out) {
    int idx = blockIdx.x * 256 + threadIdx.x;
    int bc = idx / SP;
    int b = bc / CC;
    int c = bc - b * CC;
    int sidx = b * 32 + c / 6;
    float y = (in[idx] - mean[sidx]) * rstd[sidx] * w[c] + bb[c];
    out[idx] = y / (1.f + __expf(-y));
}

// ---------------- 3x3 conv (pad=1), OC=192, f32x2 over oc-pairs ----------------
// EPI 0: affine  y = y + gs*y + gs   (extra = gb_sum [B*192])
// EPI 1: add     y = y + extra[idx]  (extra = full tensor)
template<int CIN, int EPI>
__global__ __launch_bounds__(256) void conv3x3(const float* __restrict__ in,
                                               const float* __restrict__ wgt,
                                               const float* __restrict__ bias,
                                               const float* __restrict__ extra,
                                               float* __restrict__ out) {
    const int octile = blockIdx.x;     // 6 tiles of 32 oc
    const int y0 = blockIdx.y * 8;     // 6 row tiles of 8 rows
    const int b = blockIdx.z;
    const int tid = threadIdx.x;
    const int lane = tid & 63;         // 64 spatial lanes
    const int g = tid >> 6;            // 4 oc groups of 8

    const int r  = lane >> 3;          // row within 8-row tile
    const int c0 = (lane & 7) * 6;     // 6 consecutive cols per thread

    __shared__ float s_in[8 * 10 * 52];      // 8 ci x 10 rows x 52 (pad) cols
    __shared__ float s_w[8 * 9 * 32];        // [ci][tap][oc] — oc pairs contiguous

    u64 acc[4][6];                     // 4 oc-pairs x 6 cols
    #pragma unroll
    for (int p = 0; p < 4; ++p)
        #pragma unroll
        for (int k = 0; k < 6; ++k) acc[p][k] = pack2(0.f, 0.f);

    const int nchunks = CIN / 8;
    for (int ch = 0; ch < nchunks; ++ch) {
        const int ci0 = ch * 8;
        __syncthreads();
        // stage input halo tile: rows y0-1..y0+8, cols -1..48 (col idx 0..49)
        for (int i = tid; i < 4000; i += 256) {
            int ci = i / 500;
            int rem = i - ci * 500;
            int rr = rem / 50;
            int cc2 = rem - rr * 50;
            int gy = y0 - 1 + rr;
            int gx = cc2 - 1;
            float v = 0.f;
            if (gy >= 0 && gy < HH && (unsigned)gx < (unsigned)WW)
                v = in[(((long)b * CIN + ci0 + ci) * HH + gy) * WW + gx];
            s_in[ci * 520 + rr * 52 + cc2] = v;
        }
        // stage weights transposed: s_w[ci][tap][oc]
        for (int i = tid; i < 2304; i += 256) {
            int ci = i / 288;
            int rem = i - ci * 288;
            int tap = rem >> 5;
            int oc = rem & 31;
            s_w[i] = wgt[(((long)(octile * 32 + oc) * CIN + ci0 + ci) * 9) + tap];
        }
        __syncthreads();

        #pragma unroll
        for (int ci = 0; ci < 8; ++ci) {
            const float* ibase = &s_in[ci * 520 + c0];
            #pragma unroll
            for (int dy = 0; dy < 3; ++dy) {
                // load 8-wide input window for this (ci, row) as 4 LDS.64
                const float2* rowp = (const float2*)(ibase + (r + dy) * 52);
                u64 d[8];
                #pragma unroll
                for (int j = 0; j < 4; ++j) {
                    float2 t = rowp[j];
                    d[2 * j]     = pack2(t.x, t.x);
                    d[2 * j + 1] = pack2(t.y, t.y);
                }
                #pragma unroll
                for (int dx = 0; dx < 3; ++dx) {
                    const int tap = dy * 3 + dx;
                    const u64* wp = (const u64*)&s_w[ci * 288 + tap * 32 + g * 8];
                    u64 w0 = wp[0], w1 = wp[1], w2 = wp[2], w3 = wp[3];
                    #pragma unroll
                    for (int k = 0; k < 6; ++k) {
                        u64 iv = d[k + dx];
                        acc[0][k] = fma2(w0, iv, acc[0][k]);
                        acc[1][k] = fma2(w1, iv, acc[1][k]);
                        acc[2][k] = fma2(w2, iv, acc[2][k]);
                        acc[3][k] = fma2(w3, iv, acc[3][k]);
                    }
                }
            }
        }
    }

    #pragma unroll
    for (int p = 0; p < 4; ++p) {
        int oc0 = octile * 32 + g * 8 + 2 * p;
        #pragma unroll
        for (int half = 0; half < 2; ++half) {
            int oc = oc0 + half;
            float bv = bias[oc];
            float gs = (EPI == 0) ? extra[b * CC + oc] : 0.f;
            #pragma unroll
            for (int k = 0; k < 6; ++k) {
                float lo, hi;
                unpack2(acc[p][k], lo, hi);
                float y = (half == 0 ? lo : hi) + bv;
                int idx = (((long)b * CC + oc) * HH + (y0 + r)) * WW + c0 + k;
                if (EPI == 0) y = y + gs * y + gs;
                else          y = y + extra[idx];
                out[idx] = y;
            }
        }
    }
}

// ---------------- 1x1 conv (GEMM over channels), no bias ----------------
template<int CO>
__global__ __launch_bounds__(256) void conv1x1(const float* __restrict__ in,
                                               const float* __restrict__ wgt,
                                               float* __restrict__ out) {
    const int b = blockIdx.y;
    const int p0 = blockIdx.x * 256;
    const int tid = threadIdx.x;
    __shared__ float s_w[CO * 192];
    __shared__ float s_x[16 * 256];
    for (int i = tid; i < CO * 192; i += 256) s_w[i] = wgt[i];
    float acc[CO];
    #pragma unroll
    for (int co = 0; co < CO; ++co) acc[co] = 0.f;

    for (int c0 = 0; c0 < 192; c0 += 16) {
        __syncthreads();
        for (int i = tid; i < 16 * 256; i += 256) {
            int ci = i >> 8;
            int pp = i & 255;
            s_x[i] = in[((long)b * 192 + c0 + ci) * SP + p0 + pp];
        }
        __syncthreads();
        for (int ci = 0; ci < 16; ++ci) {
            float xv = s_x[ci * 256 + tid];
            #pragma unroll
            for (int co = 0; co < CO; ++co)
                acc[co] = fmaf(s_w[co * 192 + c0 + ci], xv, acc[co]);
        }
    }
    #pragma unroll
    for (int co = 0; co < CO; ++co)
        out[((long)b * CO + co) * SP + p0 + tid] = acc[co];
}

// ---------------- cross-attention: split-K flash, f32x2, transposed smem ----------
// q: [B][16][2304]; kv: [B][32][2304] (k = ch 0..15, v = ch 16..31)
// block: 256 threads, 128 queries; thread group h = tid>>7 handles key half h.
#define KV_PAD 18
__global__ __launch_bounds__(256) void attn_kernel(const float* __restrict__ q,
                                                   const float* __restrict__ kv,
                                                   float* __restrict__ out) {
    const int b = blockIdx.y;
    const int q0 = blockIdx.x * 128;
    const int tid = threadIdx.x;
    const int qi = tid & 127;
    const int h = tid >> 7;

    __shared__ float q_s[16 * 128];
    __shared__ float k_s[256 * KV_PAD];
    __shared__ float v_s[256 * KV_PAD];
    __shared__ float m_sh[128], l_sh[128], a_sh[128 * 16];

    for (int i = tid; i < 16 * 128; i += 256) {
        int c = i >> 7;
        int p = i & 127;
        q_s[i] = q[((long)b * 16 + c) * SP + q0 + p];
    }
    __syncthreads();
    u64 qp[8];
    #pragma unroll
    for (int pc = 0; pc < 8; ++pc)
        qp[pc] = pack2(q_s[(2 * pc) * 128 + qi], q_s[(2 * pc + 1) * 128 + qi]);

    float m = -3.4e38f, l = 0.f;
    u64 acc[8];
    #pragma unroll
    for (int pc = 0; pc < 8; ++pc) acc[pc] = pack2(0.f, 0.f);

    const long kvbase = (long)b * 32 * SP;
    for (int it = 0; it < 9; ++it) {
        __syncthreads();
        // stage 256 keys (128 for each half, disjoint ranges), transposed
        for (int i = tid; i < 16 * 256; i += 256) {
            int c = i >> 8;
            int p = i & 255;
            int gk = (p < 128) ? (it * 128 + p) : (1152 + it * 128 + (p - 128));
            k_s[p * KV_PAD + c] = kv[kvbase + c * SP + gk];
            v_s[p * KV_PAD + c] = kv[kvbase + (16 + c) * SP + gk];
        }
        __syncthreads();
        const float* kbase = &k_s[(h * 128) * KV_PAD];
        const float* vbase = &v_s[(h * 128) * KV_PAD];
        #pragma unroll 2
        for (int j = 0; j < 128; ++j) {
            const u64* kj = (const u64*)(kbase + j * KV_PAD);
            u64 s2 = pack2(0.f, 0.f);
            #pragma unroll
            for (int pc = 0; pc < 8; ++pc) s2 = fma2(qp[pc], kj[pc], s2);
            float slo, shi;
            unpack2(s2, slo, shi);
            float s = (slo + shi) * 0.25f;
            if (s > m) {
                float corr = __expf(m - s);
                m = s;
                l *= corr;
                u64 c2 = pack2(corr, corr);
                #pragma unroll
                for (int pc = 0; pc < 8; ++pc)
                    acc[pc] = fma2(acc[pc], c2, pack2(0.f, 0.f));
            }
            float p = __expf(s - m);
            l += p;
            u64 p2 = pack2(p, p);
            const u64* vj = (const u64*)(vbase + j * KV_PAD);
            #pragma unroll
            for (int pc = 0; pc < 8; ++pc) acc[pc] = fma2(p2, vj[pc], acc[pc]);
        }
    }

    // merge halves
    if (h == 1) {
        m_sh[qi] = m;
        l_sh[qi] = l;
        #pragma unroll
        for (int pc = 0; pc < 8; ++pc) {
            float lo, hi;
            unpack2(acc[pc], lo, hi);
            a_sh[qi * 16 + 2 * pc] = lo;
            a_sh[qi * 16 + 2 * pc + 1] = hi;
        }
    }
    __syncthreads();
    if (h == 0) {
        float m1 = m_sh[qi], l1 = l_sh[qi];
        float M = fmaxf(m, m1);
        float e0 = __expf(m - M), e1 = __expf(m1 - M);
        float L = l * e0 + l1 * e1;
        float inv = 1.f / L;
        #pragma unroll
        for (int pc = 0; pc < 8; ++pc) {
            float lo, hi;
            unpack2(acc[pc], lo, hi);
            float o0 = (lo * e0 + a_sh[qi * 16 + 2 * pc] * e1) * inv;
            float o1 = (hi * e0 + a_sh[qi * 16 + 2 * pc + 1] * e1) * inv;
            out[((long)b * 16 + 2 * pc) * SP + q0 + qi] = o0;
            out[((long)b * 16 + 2 * pc + 1) * SP + q0 + qi] = o1;
        }
    }
}

// ---------------- launcher ----------------
extern "C" void kernel_launch(void* const* d_in, const int* in_sizes, int n_in,
                              void* d_out, int out_size) {
    const float* x       = (const float*)d_in[0];
    const float* xe      = (const float*)d_in[1];
    const float* temb    = (const float*)d_in[2];
    const float* gn1_w   = (const float*)d_in[3];
    const float* gn1_b   = (const float*)d_in[4];
    const float* conv1_w = (const float*)d_in[5];
    const float* conv1_b = (const float*)d_in[6];
    const float* aff_w   = (const float*)d_in[7];
    const float* aff_b   = (const float*)d_in[8];
    const float* gn2_w   = (const float*)d_in[9];
    const float* gn2_b   = (const float*)d_in[10];
    const float* conv2_w = (const float*)d_in[11];
    const float* conv2_b = (const float*)d_in[12];
    const float* q_w     = (const float*)d_in[13];
    const float* kv_w    = (const float*)d_in[14];
    const float* out_w   = (const float*)d_in[15];
    const float* out_b   = (const float*)d_in[16];

    float *act, *h, *xres, *qb, *kvb, *attno, *mean, *rstd, *gbsum;
    cudaGetSymbolAddress((void**)&act,   g_act);
    cudaGetSymbolAddress((void**)&h,     g_h);
    cudaGetSymbolAddress((void**)&xres,  g_xres);
    cudaGetSymbolAddress((void**)&qb,    g_q);
    cudaGetSymbolAddress((void**)&kvb,   g_kv);
    cudaGetSymbolAddress((void**)&attno, g_attnout);
    cudaGetSymbolAddress((void**)&mean,  g_mean);
    cudaGetSymbolAddress((void**)&rstd,  g_rstd);
    cudaGetSymbolAddress((void**)&gbsum, g_gbsum);

    affine_kernel<<<BB, 192>>>(temb, aff_w, aff_b, gbsum);

    gn_stats<<<BB * 32, 256>>>(x, mean, rstd);
    gn_apply<<<TOTAL / 256, 256>>>(x, mean, rstd, gn1_w, gn1_b, act);
    conv3x3<192, 0><<<dim3(6, 6, BB), 256>>>(act, conv1_w, conv1_b, gbsum, h);
    gn_stats<<<BB * 32, 256>>>(h, mean, rstd);
    gn_apply<<<TOTAL / 256, 256>>>(h, mean, rstd, gn2_w, gn2_b, act);
    conv3x3<192, 1><<<dim3(6, 6, BB), 256>>>(act, conv2_w, conv2_b, x, xres);

    conv1x1<16><<<dim3(9, BB), 256>>>(xres, q_w, qb);
    conv1x1<32><<<dim3(9, BB), 256>>>(xe, kv_w, kvb);
    attn_kernel<<<dim3(18, BB), 256>>>(qb, kvb, attno);
    conv3x3<16, 1><<<dim3(6, 6, BB), 256>>>(attno, out_w, out_b, xres, (float*)d_out);
}

// round 5
// speedup vs baseline: 1.4647x; 1.2084x over previous
#include <cuda_runtime.h>
#include <cstdint>
#include <math.h>

#define HH 48
#define WW 48
#define SP 2304
#define CC 192
#define BB 8
#define TOTAL 3538944

typedef unsigned long long u64;

// ---------------- scratch ----------------
__device__ float g_act[TOTAL];
__device__ float g_h[TOTAL];
__device__ float g_xres[TOTAL];
__device__ float g_q[BB*16*SP];
__device__ float g_kv[BB*32*SP];
__device__ float g_attnout[BB*16*SP];
__device__ float g_mean[BB*32];
__device__ float g_rstd[BB*32];
__device__ float g_gbsum[BB*CC];

// ---------------- f32x2 helpers ----------------
__device__ __forceinline__ u64 pack2(float lo, float hi) {
    u64 r; asm("mov.b64 %0, {%1, %2};" : "=l"(r) : "f"(lo), "f"(hi)); return r;
}
__device__ __forceinline__ void unpack2(u64 v, float& lo, float& hi) {
    asm("mov.b64 {%0, %1}, %2;" : "=f"(lo), "=f"(hi) : "l"(v));
}
__device__ __forceinline__ u64 fma2(u64 a, u64 b, u64 c) {
    u64 d; asm("fma.rn.f32x2 %0, %1, %2, %3;" : "=l"(d) : "l"(a), "l"(b), "l"(c)); return d;
}

__device__ __forceinline__ float warp_red(float v) {
    #pragma unroll
    for (int o = 16; o > 0; o >>= 1) v += __shfl_down_sync(0xffffffffu, v, o);
    return v;
}

__device__ __forceinline__ uint32_t to_tf32(float f) {
    uint32_t r; asm("cvt.rna.tf32.f32 %0, %1;" : "=r"(r) : "f"(f)); return r;
}

__device__ __forceinline__ void mma_tf32(float c[4], const uint32_t a[4], const uint32_t b[2]) {
    asm volatile(
        "mma.sync.aligned.m16n8k8.row.col.f32.tf32.tf32.f32 "
        "{%0,%1,%2,%3}, {%4,%5,%6,%7}, {%8,%9}, {%0,%1,%2,%3};"
        : "+f"(c[0]), "+f"(c[1]), "+f"(c[2]), "+f"(c[3])
        : "r"(a[0]), "r"(a[1]), "r"(a[2]), "r"(a[3]), "r"(b[0]), "r"(b[1]));
}

// ---------------- FeatureWiseAffine ----------------
__global__ void affine_kernel(const float* __restrict__ temb,
                              const float* __restrict__ aw,
                              const float* __restrict__ ab,
                              float* __restrict__ gbsum) {
    int b = blockIdx.x;
    int c = threadIdx.x;
    __shared__ float t[192];
    t[c] = temb[b * 192 + c];
    __syncthreads();
    float s = ab[c] + ab[192 + c];
    const float* w1 = aw + c * 192;
    const float* w2 = aw + (192 + c) * 192;
    for (int e = 0; e < 192; ++e) s = fmaf(t[e], w1[e] + w2[e], s);
    gbsum[b * 192 + c] = 0.5f * s;
}

// ---------------- GroupNorm stats ----------------
__global__ __launch_bounds__(256) void gn_stats(const float* __restrict__ in,
                                                float* __restrict__ mean,
                                                float* __restrict__ rstd) {
    int bg = blockIdx.x;
    const float* base = in + (long)bg * 13824;
    float s = 0.f, s2 = 0.f;
    for (int i = threadIdx.x; i < 13824; i += 256) {
        float v = base[i];
        s += v; s2 = fmaf(v, v, s2);
    }
    __shared__ float shs[8], shs2[8];
    int w = threadIdx.x >> 5, l = threadIdx.x & 31;
    s = warp_red(s); s2 = warp_red(s2);
    if (l == 0) { shs[w] = s; shs2[w] = s2; }
    __syncthreads();
    if (w == 0) {
        s  = (l < 8) ? shs[l]  : 0.f;
        s2 = (l < 8) ? shs2[l] : 0.f;
        s = warp_red(s); s2 = warp_red(s2);
        if (l == 0) {
            float m = s * (1.f / 13824.f);
            float var = s2 * (1.f / 13824.f) - m * m;
            mean[bg] = m;
            rstd[bg] = rsqrtf(var + 1e-5f);
        }
    }
}

// ---------------- GroupNorm apply + swish ----------------
__global__ __launch_bounds__(256) void gn_apply(const float* __restrict__ in,
                                                const float* __restrict__ mean,
                                                const float* __restrict__ rstd,
                                                const float* __restrict__ w,
                                                const float* __restrict__ bb,
                                                float* __restrict__ out) {
    int idx = blockIdx.x * 256 + threadIdx.x;
    int bc = idx / SP;
    int b = bc / CC;
    int c = bc - b * CC;
    int sidx = b * 32 + c / 6;
    float y = (in[idx] - mean[sidx]) * rstd[sidx] * w[c] + bb[c];
    out[idx] = y / (1.f + __expf(-y));
}

// ---------------- mma.sync TF32 implicit-GEMM 3x3 conv (CIN=192, OC=192) ----------
// A = weights [192 ch][K=1728] row-major; B = im2col [K][128 positions] col-major.
// One CTA per (mtile of 128 positions, batch). K staged in chunks of 32, double-buffered.
// EPI 0: y = y + gs*y + gs (extra = gbsum[B*192]); EPI 1: y += extra[idx].
#define WST 36                     // weight tile row stride (floats)
#define WTILE (192 * WST)          // 6912 u32
#define ITILE (128 * 32)           // 4096 u32
template<int EPI>
__global__ __launch_bounds__(256) void conv_mma(const float* __restrict__ in,
                                                const float* __restrict__ wgt,
                                                const float* __restrict__ bias,
                                                const float* __restrict__ extra,
                                                float* __restrict__ out) {
    extern __shared__ uint32_t sm[];
    uint32_t* Wb[2] = { sm, sm + WTILE };
    uint32_t* Ib[2] = { sm + 2 * WTILE, sm + 2 * WTILE + ITILE };

    const int mtile = blockIdx.x;   // 0..17
    const int b = blockIdx.y;       // 0..7
    const int tid = threadIdx.x;
    const int wid = tid >> 5;
    const int lane = tid & 31;
    const int g = lane >> 2;        // 0..7
    const int t = lane & 3;         // 0..3
    const int wm = wid & 3;         // 4 M tiles of 48 channels
    const int wn = wid >> 2;        // 2 N tiles of 64 positions

    // staging identity: thread owns position p, k-half khalf (16 consecutive k)
    const int p = tid & 127;
    const int khalf = tid >> 7;
    const int pg = mtile * 128 + p;
    const int py = pg / 48;
    const int px = pg - py * 48;
    const long inb = (long)b * 192 * SP;

    // ---- stage chunk 0 ----
    {
        #pragma unroll
        for (int i = 0; i < 16; ++i) {
            int k = khalf * 16 + i;
            int ci = k / 9;
            int tap = k - ci * 9;
            int dy = tap / 3;
            int dx = tap - dy * 3;
            int gy = py + dy - 1, gx = px + dx - 1;
            float v = 0.f;
            if ((unsigned)gy < (unsigned)HH && (unsigned)gx < (unsigned)WW)
                v = in[inb + (long)ci * SP + gy * WW + gx];
            Ib[0][p * 32 + (k ^ (p & 31))] = to_tf32(v);
        }
        #pragma unroll
        for (int it = 0; it < 6; ++it) {
            int idx = it * 256 + tid;
            int n = idx >> 3;
            int kq = (idx & 7) * 4;
            float4 wv = *(const float4*)(wgt + (long)n * 1728 + kq);
            uint4 u = { to_tf32(wv.x), to_tf32(wv.y), to_tf32(wv.z), to_tf32(wv.w) };
            *(uint4*)&Wb[0][n * WST + kq] = u;
        }
    }
    __syncthreads();

    float acc[3][8][4];
    #pragma unroll
    for (int i = 0; i < 3; ++i)
        #pragma unroll
        for (int j = 0; j < 8; ++j)
            #pragma unroll
            for (int q = 0; q < 4; ++q) acc[i][j][q] = 0.f;

    for (int c = 0; c < 54; ++c) {
        const int buf = c & 1;
        const bool pf = (c < 53);
        float iv[16];
        float4 wv[6];
        if (pf) {
            const int k0n = (c + 1) * 32;
            #pragma unroll
            for (int i = 0; i < 16; ++i) {
                int k = k0n + khalf * 16 + i;
                int ci = k / 9;
                int tap = k - ci * 9;
                int dy = tap / 3;
                int dx = tap - dy * 3;
                int gy = py + dy - 1, gx = px + dx - 1;
                iv[i] = 0.f;
                if ((unsigned)gy < (unsigned)HH && (unsigned)gx < (unsigned)WW)
                    iv[i] = in[inb + (long)ci * SP + gy * WW + gx];
            }
            #pragma unroll
            for (int it = 0; it < 6; ++it) {
                int idx = it * 256 + tid;
                int n = idx >> 3;
                int kq = (idx & 7) * 4;
                wv[it] = *(const float4*)(wgt + (long)n * 1728 + k0n + kq);
            }
        }

        // ---- compute on buf ----
        const uint32_t* Wp = Wb[buf];
        const uint32_t* Ip = Ib[buf];
        #pragma unroll
        for (int ks = 0; ks < 4; ++ks) {
            const int kk0 = ks * 8;
            uint32_t afr[3][4];
            #pragma unroll
            for (int i = 0; i < 3; ++i) {
                int row = wm * 48 + i * 16 + g;
                afr[i][0] = Wp[row * WST + kk0 + t];
                afr[i][1] = Wp[(row + 8) * WST + kk0 + t];
                afr[i][2] = Wp[row * WST + kk0 + t + 4];
                afr[i][3] = Wp[(row + 8) * WST + kk0 + t + 4];
            }
            uint32_t bfr[8][2];
            #pragma unroll
            for (int j = 0; j < 8; ++j) {
                int pp = wn * 64 + j * 8 + g;
                int pl = pp & 31;
                bfr[j][0] = Ip[pp * 32 + ((kk0 + t) ^ pl)];
                bfr[j][1] = Ip[pp * 32 + ((kk0 + t + 4) ^ pl)];
            }
            #pragma unroll
            for (int i = 0; i < 3; ++i)
                #pragma unroll
                for (int j = 0; j < 8; ++j)
                    mma_tf32(acc[i][j], afr[i], bfr[j]);
        }

        if (pf) {
            uint32_t* Wn = Wb[buf ^ 1];
            uint32_t* In = Ib[buf ^ 1];
            const int k0n = (c + 1) * 32;
            #pragma unroll
            for (int i = 0; i < 16; ++i) {
                int kk = khalf * 16 + i;
                In[p * 32 + (kk ^ (p & 31))] = to_tf32(iv[i]);
            }
            (void)k0n;
            #pragma unroll
            for (int it = 0; it < 6; ++it) {
                int idx = it * 256 + tid;
                int n = idx >> 3;
                int kq = (idx & 7) * 4;
                uint4 u = { to_tf32(wv[it].x), to_tf32(wv[it].y),
                            to_tf32(wv[it].z), to_tf32(wv[it].w) };
                *(uint4*)&Wn[n * WST + kq] = u;
            }
        }
        __syncthreads();
    }

    // ---- epilogue: coalesced float2 stores ----
    #pragma unroll
    for (int i = 0; i < 3; ++i) {
        const int ch0 = wm * 48 + i * 16 + g;
        const int ch1 = ch0 + 8;
        const float bv0 = bias[ch0], bv1 = bias[ch1];
        float ga0 = 0.f, ga1 = 0.f;
        if (EPI == 0) { ga0 = extra[b * CC + ch0]; ga1 = extra[b * CC + ch1]; }
        #pragma unroll
        for (int j = 0; j < 8; ++j) {
            const int pos = mtile * 128 + wn * 64 + j * 8 + 2 * t;
            long idx0 = ((long)b * CC + ch0) * SP + pos;
            long idx1 = ((long)b * CC + ch1) * SP + pos;
            float y0 = acc[i][j][0] + bv0;
            float y1 = acc[i][j][1] + bv0;
            float y2 = acc[i][j][2] + bv1;
            float y3 = acc[i][j][3] + bv1;
            if (EPI == 0) {
                y0 += ga0 * y0 + ga0; y1 += ga0 * y1 + ga0;
                y2 += ga1 * y2 + ga1; y3 += ga1 * y3 + ga1;
            } else {
                float2 e0 = *(const float2*)(extra + idx0);
                float2 e1 = *(const float2*)(extra + idx1);
                y0 += e0.x; y1 += e0.y; y2 += e1.x; y3 += e1.y;
            }
            *(float2*)(out + idx0) = make_float2(y0, y1);
            *(float2*)(out + idx1) = make_float2(y2, y3);
        }
    }
}

// ---------------- scalar 3x3 conv for the small out conv (CIN=16) ----------------
template<int CIN, int EPI>
__global__ __launch_bounds__(256) void conv3x3(const float* __restrict__ in,
                                               const float* __restrict__ wgt,
                                               const float* __restrict__ bias,
                                               const float* __restrict__ extra,
                                               float* __restrict__ out) {
    const int octile = blockIdx.x;
    const int y0 = blockIdx.y * 8;
    const int b = blockIdx.z;
    const int tid = threadIdx.x;
    const int lane = tid & 63;
    const int g = tid >> 6;

    const int r  = lane >> 3;
    const int c0 = (lane & 7) * 6;

    __shared__ float s_in[8 * 10 * 52];
    __shared__ float s_w[8 * 9 * 32];

    u64 acc[4][6];
    #pragma unroll
    for (int pq = 0; pq < 4; ++pq)
        #pragma unroll
        for (int k = 0; k < 6; ++k) acc[pq][k] = pack2(0.f, 0.f);

    const int nchunks = CIN / 8;
    for (int ch = 0; ch < nchunks; ++ch) {
        const int ci0 = ch * 8;
        __syncthreads();
        for (int i = tid; i < 4000; i += 256) {
            int ci = i / 500;
            int rem = i - ci * 500;
            int rr = rem / 50;
            int cc2 = rem - rr * 50;
            int gy = y0 - 1 + rr;
            int gx = cc2 - 1;
            float v = 0.f;
            if (gy >= 0 && gy < HH && (unsigned)gx < (unsigned)WW)
                v = in[(((long)b * CIN + ci0 + ci) * HH + gy) * WW + gx];
            s_in[ci * 520 + rr * 52 + cc2] = v;
        }
        for (int i = tid; i < 2304; i += 256) {
            int ci = i / 288;
            int rem = i - ci * 288;
            int tap = rem >> 5;
            int oc = rem & 31;
            s_w[i] = wgt[(((long)(octile * 32 + oc) * CIN + ci0 + ci) * 9) + tap];
        }
        __syncthreads();

        #pragma unroll
        for (int ci = 0; ci < 8; ++ci) {
            const float* ibase = &s_in[ci * 520 + c0];
            #pragma unroll
            for (int dy = 0; dy < 3; ++dy) {
                const float2* rowp = (const float2*)(ibase + (r + dy) * 52);
                u64 d[8];
                #pragma unroll
                for (int j = 0; j < 4; ++j) {
                    float2 tt = rowp[j];
                    d[2 * j]     = pack2(tt.x, tt.x);
                    d[2 * j + 1] = pack2(tt.y, tt.y);
                }
                #pragma unroll
                for (int dx = 0; dx < 3; ++dx) {
                    const int tap = dy * 3 + dx;
                    const u64* wp = (const u64*)&s_w[ci * 288 + tap * 32 + g * 8];
                    u64 w0 = wp[0], w1 = wp[1], w2 = wp[2], w3 = wp[3];
                    #pragma unroll
                    for (int k = 0; k < 6; ++k) {
                        u64 iv = d[k + dx];
                        acc[0][k] = fma2(w0, iv, acc[0][k]);
                        acc[1][k] = fma2(w1, iv, acc[1][k]);
                        acc[2][k] = fma2(w2, iv, acc[2][k]);
                        acc[3][k] = fma2(w3, iv, acc[3][k]);
                    }
                }
            }
        }
    }

    #pragma unroll
    for (int pq = 0; pq < 4; ++pq) {
        int oc0 = octile * 32 + g * 8 + 2 * pq;
        #pragma unroll
        for (int half = 0; half < 2; ++half) {
            int oc = oc0 + half;
            float bv = bias[oc];
            float gs = (EPI == 0) ? extra[b * CC + oc] : 0.f;
            #pragma unroll
            for (int k = 0; k < 6; ++k) {
                float lo, hiv;
                unpack2(acc[pq][k], lo, hiv);
                float y = (half == 0 ? lo : hiv) + bv;
                int idx = (((long)b * CC + oc) * HH + (y0 + r)) * WW + c0 + k;
                if (EPI == 0) y = y + gs * y + gs;
                else          y = y + extra[idx];
                out[idx] = y;
            }
        }
    }
}

// ---------------- 1x1 conv ----------------
template<int CO>
__global__ __launch_bounds__(256) void conv1x1(const float* __restrict__ in,
                                               const float* __restrict__ wgt,
                                               float* __restrict__ out) {
    const int b = blockIdx.y;
    const int p0 = blockIdx.x * 256;
    const int tid = threadIdx.x;
    __shared__ float s_w[CO * 192];
    __shared__ float s_x[16 * 256];
    for (int i = tid; i < CO * 192; i += 256) s_w[i] = wgt[i];
    float acc[CO];
    #pragma unroll
    for (int co = 0; co < CO; ++co) acc[co] = 0.f;

    for (int c0 = 0; c0 < 192; c0 += 16) {
        __syncthreads();
        for (int i = tid; i < 16 * 256; i += 256) {
            int ci = i >> 8;
            int pp = i & 255;
            s_x[i] = in[((long)b * 192 + c0 + ci) * SP + p0 + pp];
        }
        __syncthreads();
        for (int ci = 0; ci < 16; ++ci) {
            float xv = s_x[ci * 256 + tid];
            #pragma unroll
            for (int co = 0; co < CO; ++co)
                acc[co] = fmaf(s_w[co * 192 + c0 + ci], xv, acc[co]);
        }
    }
    #pragma unroll
    for (int co = 0; co < CO; ++co)
        out[((long)b * CO + co) * SP + p0 + tid] = acc[co];
}

// ---------------- cross-attention (split-K flash, f32x2) ----------------
#define KV_PAD 18
__global__ __launch_bounds__(256) void attn_kernel(const float* __restrict__ q,
                                                   const float* __restrict__ kv,
                                                   float* __restrict__ out) {
    const int b = blockIdx.y;
    const int q0 = blockIdx.x * 128;
    const int tid = threadIdx.x;
    const int qi = tid & 127;
    const int h = tid >> 7;

    __shared__ float q_s[16 * 128];
    __shared__ float k_s[256 * KV_PAD];
    __shared__ float v_s[256 * KV_PAD];
    __shared__ float m_sh[128], l_sh[128], a_sh[128 * 16];

    for (int i = tid; i < 16 * 128; i += 256) {
        int c = i >> 7;
        int p = i & 127;
        q_s[i] = q[((long)b * 16 + c) * SP + q0 + p];
    }
    __syncthreads();
    u64 qp[8];
    #pragma unroll
    for (int pc = 0; pc < 8; ++pc)
        qp[pc] = pack2(q_s[(2 * pc) * 128 + qi], q_s[(2 * pc + 1) * 128 + qi]);

    float m = -3.4e38f, l = 0.f;
    u64 acc[8];
    #pragma unroll
    for (int pc = 0; pc < 8; ++pc) acc[pc] = pack2(0.f, 0.f);

    const long kvbase = (long)b * 32 * SP;
    for (int it = 0; it < 9; ++it) {
        __syncthreads();
        for (int i = tid; i < 16 * 256; i += 256) {
            int c = i >> 8;
            int p = i & 255;
            int gk = (p < 128) ? (it * 128 + p) : (1152 + it * 128 + (p - 128));
            k_s[p * KV_PAD + c] = kv[kvbase + c * SP + gk];
            v_s[p * KV_PAD + c] = kv[kvbase + (16 + c) * SP + gk];
        }
        __syncthreads();
        const float* kbase = &k_s[(h * 128) * KV_PAD];
        const float* vbase = &v_s[(h * 128) * KV_PAD];
        #pragma unroll 2
        for (int j = 0; j < 128; ++j) {
            const u64* kj = (const u64*)(kbase + j * KV_PAD);
            u64 s2 = pack2(0.f, 0.f);
            #pragma unroll
            for (int pc = 0; pc < 8; ++pc) s2 = fma2(qp[pc], kj[pc], s2);
            float slo, shi;
            unpack2(s2, slo, shi);
            float s = (slo + shi) * 0.25f;
            if (s > m) {
                float corr = __expf(m - s);
                m = s;
                l *= corr;
                u64 c2 = pack2(corr, corr);
                #pragma unroll
                for (int pc = 0; pc < 8; ++pc)
                    acc[pc] = fma2(acc[pc], c2, pack2(0.f, 0.f));
            }
            float p = __expf(s - m);
            l += p;
            u64 p2 = pack2(p, p);
            const u64* vj = (const u64*)(vbase + j * KV_PAD);
            #pragma unroll
            for (int pc = 0; pc < 8; ++pc) acc[pc] = fma2(p2, vj[pc], acc[pc]);
        }
    }

    if (h == 1) {
        m_sh[qi] = m;
        l_sh[qi] = l;
        #pragma unroll
        for (int pc = 0; pc < 8; ++pc) {
            float lo, hi;
            unpack2(acc[pc], lo, hi);
            a_sh[qi * 16 + 2 * pc] = lo;
            a_sh[qi * 16 + 2 * pc + 1] = hi;
        }
    }
    __syncthreads();
    if (h == 0) {
        float m1 = m_sh[qi], l1 = l_sh[qi];
        float M = fmaxf(m, m1);
        float e0 = __expf(m - M), e1 = __expf(m1 - M);
        float L = l * e0 + l1 * e1;
        float inv = 1.f / L;
        #pragma unroll
        for (int pc = 0; pc < 8; ++pc) {
            float lo, hi;
            unpack2(acc[pc], lo, hi);
            float o0 = (lo * e0 + a_sh[qi * 16 + 2 * pc] * e1) * inv;
            float o1 = (hi * e0 + a_sh[qi * 16 + 2 * pc + 1] * e1) * inv;
            out[((long)b * 16 + 2 * pc) * SP + q0 + qi] = o0;
            out[((long)b * 16 + 2 * pc + 1) * SP + q0 + qi] = o1;
        }
    }
}

// ---------------- launcher ----------------
extern "C" void kernel_launch(void* const* d_in, const int* in_sizes, int n_in,
                              void* d_out, int out_size) {
    const float* x       = (const float*)d_in[0];
    const float* xe      = (const float*)d_in[1];
    const float* temb    = (const float*)d_in[2];
    const float* gn1_w   = (const float*)d_in[3];
    const float* gn1_b   = (const float*)d_in[4];
    const float* conv1_w = (const float*)d_in[5];
    const float* conv1_b = (const float*)d_in[6];
    const float* aff_w   = (const float*)d_in[7];
    const float* aff_b   = (const float*)d_in[8];
    const float* gn2_w   = (const float*)d_in[9];
    const float* gn2_b   = (const float*)d_in[10];
    const float* conv2_w = (const float*)d_in[11];
    const float* conv2_b = (const float*)d_in[12];
    const float* q_w     = (const float*)d_in[13];
    const float* kv_w    = (const float*)d_in[14];
    const float* out_w   = (const float*)d_in[15];
    const float* out_b   = (const float*)d_in[16];

    float *act, *h, *xres, *qb, *kvb, *attno, *mean, *rstd, *gbsum;
    cudaGetSymbolAddress((void**)&act,   g_act);
    cudaGetSymbolAddress((void**)&h,     g_h);
    cudaGetSymbolAddress((void**)&xres,  g_xres);
    cudaGetSymbolAddress((void**)&qb,    g_q);
    cudaGetSymbolAddress((void**)&kvb,   g_kv);
    cudaGetSymbolAddress((void**)&attno, g_attnout);
    cudaGetSymbolAddress((void**)&mean,  g_mean);
    cudaGetSymbolAddress((void**)&rstd,  g_rstd);
    cudaGetSymbolAddress((void**)&gbsum, g_gbsum);

    const int DSM = (2 * WTILE + 2 * ITILE) * 4;  // 88064 bytes
    cudaFuncSetAttribute(conv_mma<0>, cudaFuncAttributeMaxDynamicSharedMemorySize, DSM);
    cudaFuncSetAttribute(conv_mma<1>, cudaFuncAttributeMaxDynamicSharedMemorySize, DSM);

    affine_kernel<<<BB, 192>>>(temb, aff_w, aff_b, gbsum);

    gn_stats<<<BB * 32, 256>>>(x, mean, rstd);
    gn_apply<<<TOTAL / 256, 256>>>(x, mean, rstd, gn1_w, gn1_b, act);
    conv_mma<0><<<dim3(18, BB), 256, DSM>>>(act, conv1_w, conv1_b, gbsum, h);
    gn_stats<<<BB * 32, 256>>>(h, mean, rstd);
    gn_apply<<<TOTAL / 256, 256>>>(h, mean, rstd, gn2_w, gn2_b, act);
    conv_mma<1><<<dim3(18, BB), 256, DSM>>>(act, conv2_w, conv2_b, x, xres);

    conv1x1<16><<<dim3(9, BB), 256>>>(xres, q_w, qb);
    conv1x1<32><<<dim3(9, BB), 256>>>(xe, kv_w, kvb);
    attn_kernel<<<dim3(18, BB), 256>>>(qb, kvb, attno);
    conv3x3<16, 1><<<dim3(6, 6, BB), 256>>>(attno, out_w, out_b, xres, (float*)d_out);
}

// round 6
// speedup vs baseline: 2.1942x; 1.4980x over previous
#include <cuda_runtime.h>
#include <cstdint>
#include <math.h>

#define HH 48
#define WW 48
#define SP 2304
#define CC 192
#define BB 8
#define TOTAL 3538944

typedef unsigned long long u64;

// ---------------- scratch ----------------
__device__ float g_pad[BB*CC*2500];   // zero-bordered [b][c][50][50]; borders stay 0 (.bss)
__device__ float g_wt[CC*1728];       // tap-major transposed weights
__device__ float g_h[TOTAL];
__device__ float g_xres[TOTAL];
__device__ float g_q[BB*16*SP];
__device__ float g_kv[BB*32*SP];
__device__ float g_attnout[BB*16*SP];
__device__ float g_mean[BB*32];
__device__ float g_rstd[BB*32];
__device__ float g_gbsum[BB*CC];

// ---------------- f32x2 helpers ----------------
__device__ __forceinline__ u64 pack2(float lo, float hi) {
    u64 r; asm("mov.b64 %0, {%1, %2};" : "=l"(r) : "f"(lo), "f"(hi)); return r;
}
__device__ __forceinline__ void unpack2(u64 v, float& lo, float& hi) {
    asm("mov.b64 {%0, %1}, %2;" : "=f"(lo), "=f"(hi) : "l"(v));
}
__device__ __forceinline__ u64 fma2(u64 a, u64 b, u64 c) {
    u64 d; asm("fma.rn.f32x2 %0, %1, %2, %3;" : "=l"(d) : "l"(a), "l"(b), "l"(c)); return d;
}

__device__ __forceinline__ float warp_red(float v) {
    #pragma unroll
    for (int o = 16; o > 0; o >>= 1) v += __shfl_down_sync(0xffffffffu, v, o);
    return v;
}

__device__ __forceinline__ void mma_tf32(float c[4], const uint32_t a[4], const uint32_t b[2]) {
    asm volatile(
        "mma.sync.aligned.m16n8k8.row.col.f32.tf32.tf32.f32 "
        "{%0,%1,%2,%3}, {%4,%5,%6,%7}, {%8,%9}, {%0,%1,%2,%3};"
        : "+f"(c[0]), "+f"(c[1]), "+f"(c[2]), "+f"(c[3])
        : "r"(a[0]), "r"(a[1]), "r"(a[2]), "r"(a[3]), "r"(b[0]), "r"(b[1]));
}

// ---------------- cp.async helpers ----------------
__device__ __forceinline__ uint32_t smaddr(const void* p) {
    return (uint32_t)__cvta_generic_to_shared(p);
}
__device__ __forceinline__ void cp4(uint32_t dst, const void* src) {
    asm volatile("cp.async.ca.shared.global [%0], [%1], 4;" :: "r"(dst), "l"(src));
}
__device__ __forceinline__ void cp16(uint32_t dst, const void* src) {
    asm volatile("cp.async.cg.shared.global [%0], [%1], 16;" :: "r"(dst), "l"(src));
}
#define CP_COMMIT() asm volatile("cp.async.commit_group;" ::: "memory")
#define CP_WAIT2()  asm volatile("cp.async.wait_group 2;" ::: "memory")

// ---------------- FeatureWiseAffine ----------------
__global__ void affine_kernel(const float* __restrict__ temb,
                              const float* __restrict__ aw,
                              const float* __restrict__ ab,
                              float* __restrict__ gbsum) {
    int b = blockIdx.x;
    int c = threadIdx.x;
    __shared__ float t[192];
    t[c] = temb[b * 192 + c];
    __syncthreads();
    float s = ab[c] + ab[192 + c];
    const float* w1 = aw + c * 192;
    const float* w2 = aw + (192 + c) * 192;
    for (int e = 0; e < 192; ++e) s = fmaf(t[e], w1[e] + w2[e], s);
    gbsum[b * 192 + c] = 0.5f * s;
}

// ---------------- weight transpose: k natural (ci*9+tap) -> tap-major (tap*192+ci) ----
__global__ __launch_bounds__(256) void wt_transpose(const float* __restrict__ w,
                                                    float* __restrict__ o) {
    int i = blockIdx.x * 256 + threadIdx.x;
    if (i < CC * 1728) {
        int n = i / 1728;
        int k = i - n * 1728;
        int ci = k / 9;
        int tap = k - ci * 9;
        o[n * 1728 + tap * 192 + ci] = w[i];
    }
}

// ---------------- GroupNorm stats ----------------
__global__ __launch_bounds__(256) void gn_stats(const float* __restrict__ in,
                                                float* __restrict__ mean,
                                                float* __restrict__ rstd) {
    int bg = blockIdx.x;
    const float* base = in + (long)bg * 13824;
    float s = 0.f, s2 = 0.f;
    for (int i = threadIdx.x; i < 13824; i += 256) {
        float v = base[i];
        s += v; s2 = fmaf(v, v, s2);
    }
    __shared__ float shs[8], shs2[8];
    int w = threadIdx.x >> 5, l = threadIdx.x & 31;
    s = warp_red(s); s2 = warp_red(s2);
    if (l == 0) { shs[w] = s; shs2[w] = s2; }
    __syncthreads();
    if (w == 0) {
        s  = (l < 8) ? shs[l]  : 0.f;
        s2 = (l < 8) ? shs2[l] : 0.f;
        s = warp_red(s); s2 = warp_red(s2);
        if (l == 0) {
            float m = s * (1.f / 13824.f);
            float var = s2 * (1.f / 13824.f) - m * m;
            mean[bg] = m;
            rstd[bg] = rsqrtf(var + 1e-5f);
        }
    }
}

// ---------------- GroupNorm apply + swish -> padded [b][c][50][50] ----------------
__global__ __launch_bounds__(256) void gn_apply_pad(const float* __restrict__ in,
                                                    const float* __restrict__ mean,
                                                    const float* __restrict__ rstd,
                                                    const float* __restrict__ w,
                                                    const float* __restrict__ bb,
                                                    float* __restrict__ outpad) {
    int idx = blockIdx.x * 256 + threadIdx.x;
    int bc = idx / SP;
    int sp = idx - bc * SP;
    int b = bc / CC;
    int c = bc - b * CC;
    int sidx = b * 32 + c / 6;
    float y = (in[idx] - mean[sidx]) * rstd[sidx] * w[c] + bb[c];
    y = y / (1.f + __expf(-y));
    int py = sp / 48, px = sp - py * 48;
    outpad[(size_t)bc * 2500 + (py + 1) * 50 + (px + 1)] = y;
}

// ---------------- mma.sync TF32 implicit-GEMM 3x3 conv, cp.async 4-stage ----------
// A = weights [192][k' (tap-major)] ; B = im2col [k'][128 positions], XOR swizzled.
// EPI 0: y = y + gs*y + gs (extra = gbsum); EPI 1: y += extra[idx].
#define WST 36
#define ASZ (192 * WST)   // 6912 u32
#define BSZ (32 * 128)    // 4096 u32
#define STG (ASZ + BSZ)   // 11008 u32 per stage
template<int EPI>
__global__ __launch_bounds__(256) void conv_mma(const float* __restrict__ pad,
                                                const float* __restrict__ wt,
                                                const float* __restrict__ bias,
                                                const float* __restrict__ extra,
                                                float* __restrict__ out) {
    extern __shared__ uint32_t sm[];

    const int mtile = blockIdx.x;   // 0..17
    const int b = blockIdx.y;       // 0..7
    const int tid = threadIdx.x;
    const int wid = tid >> 5;
    const int lane = tid & 31;
    const int g = lane >> 2;
    const int t = lane & 3;
    const int wm = wid & 3;
    const int wn = wid >> 2;

    const int p = tid & 127;
    const int khalf = tid >> 7;
    const int pg = mtile * 128 + p;
    const int py = pg / 48;
    const int px = pg - py * 48;
    const float* padb = pad + (size_t)b * CC * 2500;

    // stage chunk c into stage buffer
    auto stage = [&](int c) {
        uint32_t* buf = sm + (c & 3) * STG;
        const int tap = c / 6;
        const int ci0 = (c - tap * 6) * 32;
        const int dy = tap / 3;
        const int dx = tap - dy * 3;
        // B: im2col, 16 channels per thread (ci0+khalf*16 .. +15), position p
        const float* bsrc = padb + (size_t)(ci0 + khalf * 16) * 2500
                          + (py + dy) * 50 + (px + dx);
        uint32_t* Bs = buf + ASZ;
        #pragma unroll
        for (int i = 0; i < 16; ++i) {
            int kk = khalf * 16 + i;
            cp4(smaddr(&Bs[kk * 128 + (p ^ ((kk & 3) * 8))]), bsrc + (size_t)i * 2500);
        }
        // A: weights, 6 x 16B per thread
        #pragma unroll
        for (int it = 0; it < 6; ++it) {
            int idx = it * 256 + tid;
            int n = idx >> 3;
            int kq = (idx & 7) * 4;
            cp16(smaddr(&buf[n * WST + kq]), wt + (size_t)n * 1728 + c * 32 + kq);
        }
    };

    stage(0); CP_COMMIT();
    stage(1); CP_COMMIT();
    stage(2); CP_COMMIT();

    float acc[3][8][4];
    #pragma unroll
    for (int i = 0; i < 3; ++i)
        #pragma unroll
        for (int j = 0; j < 8; ++j)
            #pragma unroll
            for (int q = 0; q < 4; ++q) acc[i][j][q] = 0.f;

    for (int c = 0; c < 54; ++c) {
        CP_WAIT2();
        __syncthreads();
        const uint32_t* Wp = sm + (c & 3) * STG;
        const uint32_t* Ip = Wp + ASZ;
        #pragma unroll
        for (int ks = 0; ks < 4; ++ks) {
            const int kk0 = ks * 8;
            uint32_t afr[3][4];
            #pragma unroll
            for (int i = 0; i < 3; ++i) {
                int row = wm * 48 + i * 16 + g;
                afr[i][0] = Wp[row * WST + kk0 + t];
                afr[i][1] = Wp[(row + 8) * WST + kk0 + t];
                afr[i][2] = Wp[row * WST + kk0 + t + 4];
                afr[i][3] = Wp[(row + 8) * WST + kk0 + t + 4];
            }
            uint32_t bfr[8][2];
            #pragma unroll
            for (int j = 0; j < 8; ++j) {
                int pp = wn * 64 + j * 8 + g;
                int ppx = pp ^ (t * 8);
                bfr[j][0] = Ip[(kk0 + t) * 128 + ppx];
                bfr[j][1] = Ip[(kk0 + t + 4) * 128 + ppx];
            }
            #pragma unroll
            for (int i = 0; i < 3; ++i)
                #pragma unroll
                for (int j = 0; j < 8; ++j)
                    mma_tf32(acc[i][j], afr[i], bfr[j]);
        }
        if (c + 3 < 54) stage(c + 3);
        CP_COMMIT();
    }

    // ---- epilogue: coalesced float2 stores ----
    #pragma unroll
    for (int i = 0; i < 3; ++i) {
        const int ch0 = wm * 48 + i * 16 + g;
        const int ch1 = ch0 + 8;
        const float bv0 = bias[ch0], bv1 = bias[ch1];
        float ga0 = 0.f, ga1 = 0.f;
        if (EPI == 0) { ga0 = extra[b * CC + ch0]; ga1 = extra[b * CC + ch1]; }
        #pragma unroll
        for (int j = 0; j < 8; ++j) {
            const int pos = mtile * 128 + wn * 64 + j * 8 + 2 * t;
            long idx0 = ((long)b * CC + ch0) * SP + pos;
            long idx1 = ((long)b * CC + ch1) * SP + pos;
            float y0 = acc[i][j][0] + bv0;
            float y1 = acc[i][j][1] + bv0;
            float y2 = acc[i][j][2] + bv1;
            float y3 = acc[i][j][3] + bv1;
            if (EPI == 0) {
                y0 += ga0 * y0 + ga0; y1 += ga0 * y1 + ga0;
                y2 += ga1 * y2 + ga1; y3 += ga1 * y3 + ga1;
            } else {
                float2 e0 = *(const float2*)(extra + idx0);
                float2 e1 = *(const float2*)(extra + idx1);
                y0 += e0.x; y1 += e0.y; y2 += e1.x; y3 += e1.y;
            }
            *(float2*)(out + idx0) = make_float2(y0, y1);
            *(float2*)(out + idx1) = make_float2(y2, y3);
        }
    }
}

// ---------------- scalar 3x3 conv for the small out conv (CIN=16) ----------------
template<int CIN, int EPI>
__global__ __launch_bounds__(256) void conv3x3(const float* __restrict__ in,
                                               const float* __restrict__ wgt,
                                               const float* __restrict__ bias,
                                               const float* __restrict__ extra,
                                               float* __restrict__ out) {
    const int octile = blockIdx.x;
    const int y0 = blockIdx.y * 8;
    const int b = blockIdx.z;
    const int tid = threadIdx.x;
    const int lane = tid & 63;
    const int g = tid >> 6;

    const int r  = lane >> 3;
    const int c0 = (lane & 7) * 6;

    __shared__ float s_in[8 * 10 * 52];
    __shared__ float s_w[8 * 9 * 32];

    u64 acc[4][6];
    #pragma unroll
    for (int pq = 0; pq < 4; ++pq)
        #pragma unroll
        for (int k = 0; k < 6; ++k) acc[pq][k] = pack2(0.f, 0.f);

    const int nchunks = CIN / 8;
    for (int ch = 0; ch < nchunks; ++ch) {
        const int ci0 = ch * 8;
        __syncthreads();
        for (int i = tid; i < 4000; i += 256) {
            int ci = i / 500;
            int rem = i - ci * 500;
            int rr = rem / 50;
            int cc2 = rem - rr * 50;
            int gy = y0 - 1 + rr;
            int gx = cc2 - 1;
            float v = 0.f;
            if (gy >= 0 && gy < HH && (unsigned)gx < (unsigned)WW)
                v = in[(((long)b * CIN + ci0 + ci) * HH + gy) * WW + gx];
            s_in[ci * 520 + rr * 52 + cc2] = v;
        }
        for (int i = tid; i < 2304; i += 256) {
            int ci = i / 288;
            int rem = i - ci * 288;
            int tap = rem >> 5;
            int oc = rem & 31;
            s_w[i] = wgt[(((long)(octile * 32 + oc) * CIN + ci0 + ci) * 9) + tap];
        }
        __syncthreads();

        #pragma unroll
        for (int ci = 0; ci < 8; ++ci) {
            const float* ibase = &s_in[ci * 520 + c0];
            #pragma unroll
            for (int dy = 0; dy < 3; ++dy) {
                const float2* rowp = (const float2*)(ibase + (r + dy) * 52);
                u64 d[8];
                #pragma unroll
                for (int j = 0; j < 4; ++j) {
                    float2 tt = rowp[j];
                    d[2 * j]     = pack2(tt.x, tt.x);
                    d[2 * j + 1] = pack2(tt.y, tt.y);
                }
                #pragma unroll
                for (int dx = 0; dx < 3; ++dx) {
                    const int tap = dy * 3 + dx;
                    const u64* wp = (const u64*)&s_w[ci * 288 + tap * 32 + g * 8];
                    u64 w0 = wp[0], w1 = wp[1], w2 = wp[2], w3 = wp[3];
                    #pragma unroll
                    for (int k = 0; k < 6; ++k) {
                        u64 iv = d[k + dx];
                        acc[0][k] = fma2(w0, iv, acc[0][k]);
                        acc[1][k] = fma2(w1, iv, acc[1][k]);
                        acc[2][k] = fma2(w2, iv, acc[2][k]);
                        acc[3][k] = fma2(w3, iv, acc[3][k]);
                    }
                }
            }
        }
    }

    #pragma unroll
    for (int pq = 0; pq < 4; ++pq) {
        int oc0 = octile * 32 + g * 8 + 2 * pq;
        #pragma unroll
        for (int half = 0; half < 2; ++half) {
            int oc = oc0 + half;
            float bv = bias[oc];
            float gs = (EPI == 0) ? extra[b * CC + oc] : 0.f;
            #pragma unroll
            for (int k = 0; k < 6; ++k) {
                float lo, hiv;
                unpack2(acc[pq][k], lo, hiv);
                float y = (half == 0 ? lo : hiv) + bv;
                int idx = (((long)b * CC + oc) * HH + (y0 + r)) * WW + c0 + k;
                if (EPI == 0) y = y + gs * y + gs;
                else          y = y + extra[idx];
                out[idx] = y;
            }
        }
    }
}

// ---------------- 1x1 conv ----------------
template<int CO>
__global__ __launch_bounds__(256) void conv1x1(const float* __restrict__ in,
                                               const float* __restrict__ wgt,
                                               float* __restrict__ out) {
    const int b = blockIdx.y;
    const int p0 = blockIdx.x * 256;
    const int tid = threadIdx.x;
    __shared__ float s_w[CO * 192];
    __shared__ float s_x[16 * 256];
    for (int i = tid; i < CO * 192; i += 256) s_w[i] = wgt[i];
    float acc[CO];
    #pragma unroll
    for (int co = 0; co < CO; ++co) acc[co] = 0.f;

    for (int c0 = 0; c0 < 192; c0 += 16) {
        __syncthreads();
        for (int i = tid; i < 16 * 256; i += 256) {
            int ci = i >> 8;
            int pp = i & 255;
            s_x[i] = in[((long)b * 192 + c0 + ci) * SP + p0 + pp];
        }
        __syncthreads();
        for (int ci = 0; ci < 16; ++ci) {
            float xv = s_x[ci * 256 + tid];
            #pragma unroll
            for (int co = 0; co < CO; ++co)
                acc[co] = fmaf(s_w[co * 192 + c0 + ci], xv, acc[co]);
        }
    }
    #pragma unroll
    for (int co = 0; co < CO; ++co)
        out[((long)b * CO + co) * SP + p0 + tid] = acc[co];
}

// ---------------- cross-attention (split-K flash, f32x2) ----------------
#define KV_PAD 18
__global__ __launch_bounds__(256) void attn_kernel(const float* __restrict__ q,
                                                   const float* __restrict__ kv,
                                                   float* __restrict__ out) {
    const int b = blockIdx.y;
    const int q0 = blockIdx.x * 128;
    const int tid = threadIdx.x;
    const int qi = tid & 127;
    const int h = tid >> 7;

    __shared__ float q_s[16 * 128];
    __shared__ float k_s[256 * KV_PAD];
    __shared__ float v_s[256 * KV_PAD];
    __shared__ float m_sh[128], l_sh[128], a_sh[128 * 16];

    for (int i = tid; i < 16 * 128; i += 256) {
        int c = i >> 7;
        int p = i & 127;
        q_s[i] = q[((long)b * 16 + c) * SP + q0 + p];
    }
    __syncthreads();
    u64 qp[8];
    #pragma unroll
    for (int pc = 0; pc < 8; ++pc)
        qp[pc] = pack2(q_s[(2 * pc) * 128 + qi], q_s[(2 * pc + 1) * 128 + qi]);

    float m = -3.4e38f, l = 0.f;
    u64 acc[8];
    #pragma unroll
    for (int pc = 0; pc < 8; ++pc) acc[pc] = pack2(0.f, 0.f);

    const long kvbase = (long)b * 32 * SP;
    for (int it = 0; it < 9; ++it) {
        __syncthreads();
        for (int i = tid; i < 16 * 256; i += 256) {
            int c = i >> 8;
            int p = i & 255;
            int gk = (p < 128) ? (it * 128 + p) : (1152 + it * 128 + (p - 128));
            k_s[p * KV_PAD + c] = kv[kvbase + c * SP + gk];
            v_s[p * KV_PAD + c] = kv[kvbase + (16 + c) * SP + gk];
        }
        __syncthreads();
        const float* kbase = &k_s[(h * 128) * KV_PAD];
        const float* vbase = &v_s[(h * 128) * KV_PAD];
        #pragma unroll 2
        for (int j = 0; j < 128; ++j) {
            const u64* kj = (const u64*)(kbase + j * KV_PAD);
            u64 s2 = pack2(0.f, 0.f);
            #pragma unroll
            for (int pc = 0; pc < 8; ++pc) s2 = fma2(qp[pc], kj[pc], s2);
            float slo, shi;
            unpack2(s2, slo, shi);
            float s = (slo + shi) * 0.25f;
            if (s > m) {
                float corr = __expf(m - s);
                m = s;
                l *= corr;
                u64 c2 = pack2(corr, corr);
                #pragma unroll
                for (int pc = 0; pc < 8; ++pc)
                    acc[pc] = fma2(acc[pc], c2, pack2(0.f, 0.f));
            }
            float p = __expf(s - m);
            l += p;
            u64 p2 = pack2(p, p);
            const u64* vj = (const u64*)(vbase + j * KV_PAD);
            #pragma unroll
            for (int pc = 0; pc < 8; ++pc) acc[pc] = fma2(p2, vj[pc], acc[pc]);
        }
    }

    if (h == 1) {
        m_sh[qi] = m;
        l_sh[qi] = l;
        #pragma unroll
        for (int pc = 0; pc < 8; ++pc) {
            float lo, hi;
            unpack2(acc[pc], lo, hi);
            a_sh[qi * 16 + 2 * pc] = lo;
            a_sh[qi * 16 + 2 * pc + 1] = hi;
        }
    }
    __syncthreads();
    if (h == 0) {
        float m1 = m_sh[qi], l1 = l_sh[qi];
        float M = fmaxf(m, m1);
        float e0 = __expf(m - M), e1 = __expf(m1 - M);
        float L = l * e0 + l1 * e1;
        float inv = 1.f / L;
        #pragma unroll
        for (int pc = 0; pc < 8; ++pc) {
            float lo, hi;
            unpack2(acc[pc], lo, hi);
            float o0 = (lo * e0 + a_sh[qi * 16 + 2 * pc] * e1) * inv;
            float o1 = (hi * e0 + a_sh[qi * 16 + 2 * pc + 1] * e1) * inv;
            out[((long)b * 16 + 2 * pc) * SP + q0 + qi] = o0;
            out[((long)b * 16 + 2 * pc + 1) * SP + q0 + qi] = o1;
        }
    }
}

// ---------------- launcher ----------------
extern "C" void kernel_launch(void* const* d_in, const int* in_sizes, int n_in,
                              void* d_out, int out_size) {
    const float* x       = (const float*)d_in[0];
    const float* xe      = (const float*)d_in[1];
    const float* temb    = (const float*)d_in[2];
    const float* gn1_w   = (const float*)d_in[3];
    const float* gn1_b   = (const float*)d_in[4];
    const float* conv1_w = (const float*)d_in[5];
    const float* conv1_b = (const float*)d_in[6];
    const float* aff_w   = (const float*)d_in[7];
    const float* aff_b   = (const float*)d_in[8];
    const float* gn2_w   = (const float*)d_in[9];
    const float* gn2_b   = (const float*)d_in[10];
    const float* conv2_w = (const float*)d_in[11];
    const float* conv2_b = (const float*)d_in[12];
    const float* q_w     = (const float*)d_in[13];
    const float* kv_w    = (const float*)d_in[14];
    const float* out_w   = (const float*)d_in[15];
    const float* out_b   = (const float*)d_in[16];

    float *padp, *wtp, *h, *xres, *qb, *kvb, *attno, *mean, *rstd, *gbsum;
    cudaGetSymbolAddress((void**)&padp,  g_pad);
    cudaGetSymbolAddress((void**)&wtp,   g_wt);
    cudaGetSymbolAddress((void**)&h,     g_h);
    cudaGetSymbolAddress((void**)&xres,  g_xres);
    cudaGetSymbolAddress((void**)&qb,    g_q);
    cudaGetSymbolAddress((void**)&kvb,   g_kv);
    cudaGetSymbolAddress((void**)&attno, g_attnout);
    cudaGetSymbolAddress((void**)&mean,  g_mean);
    cudaGetSymbolAddress((void**)&rstd,  g_rstd);
    cudaGetSymbolAddress((void**)&gbsum, g_gbsum);

    const int DSM = 4 * STG * 4;   // 176128 bytes
    cudaFuncSetAttribute(conv_mma<0>, cudaFuncAttributeMaxDynamicSharedMemorySize, DSM);
    cudaFuncSetAttribute(conv_mma<1>, cudaFuncAttributeMaxDynamicSharedMemorySize, DSM);

    affine_kernel<<<BB, 192>>>(temb, aff_w, aff_b, gbsum);

    gn_stats<<<BB * 32, 256>>>(x, mean, rstd);
    gn_apply_pad<<<TOTAL / 256, 256>>>(x, mean, rstd, gn1_w, gn1_b, padp);
    wt_transpose<<<1296, 256>>>(conv1_w, wtp);
    conv_mma<0><<<dim3(18, BB), 256, DSM>>>(padp, wtp, conv1_b, gbsum, h);

    gn_stats<<<BB * 32, 256>>>(h, mean, rstd);
    gn_apply_pad<<<TOTAL / 256, 256>>>(h, mean, rstd, gn2_w, gn2_b, padp);
    wt_transpose<<<1296, 256>>>(conv2_w, wtp);
    conv_mma<1><<<dim3(18, BB), 256, DSM>>>(padp, wtp, conv2_b, x, xres);

    conv1x1<16><<<dim3(9, BB), 256>>>(xres, q_w, qb);
    conv1x1<32><<<dim3(9, BB), 256>>>(xe, kv_w, kvb);
    attn_kernel<<<dim3(18, BB), 256>>>(qb, kvb, attno);
    conv3x3<16, 1><<<dim3(6, 6, BB), 256>>>(attno, out_w, out_b, xres, (float*)d_out);
}

// round 7
// speedup vs baseline: 2.7771x; 1.2657x over previous
#include <cuda_runtime.h>
#include <cstdint>
#include <math.h>

#define HH 48
#define WW 48
#define SP 2304
#define CC 192
#define BB 8
#define TOTAL 3538944

typedef unsigned long long u64;

// ---------------- scratch ----------------
__device__ float g_pad[BB*CC*2500];    // zero-bordered [b][c][50][50]
__device__ float g_pad2[BB*16*2600];   // zero-bordered [b][c][52][50] (attn out)
__device__ float g_wt[CC*1728];        // conv1 weights tap-major
__device__ float g_wtB[CC*1728];       // conv2 weights tap-major
__device__ float g_wt2[CC*160];        // out conv weights tap-major, K padded to 160 (zeros)
__device__ float g_h[TOTAL];
__device__ float g_xres[TOTAL];
__device__ float g_q[BB*16*SP];
__device__ float g_kv[BB*32*SP];
__device__ float g_mean[BB*32];
__device__ float g_rstd[BB*32];
__device__ float g_gbsum[BB*CC];

// ---------------- helpers ----------------
__device__ __forceinline__ float warp_red(float v) {
    #pragma unroll
    for (int o = 16; o > 0; o >>= 1) v += __shfl_down_sync(0xffffffffu, v, o);
    return v;
}
__device__ __forceinline__ uint32_t to_tf32(float f) {
    uint32_t r; asm("cvt.rna.tf32.f32 %0, %1;" : "=r"(r) : "f"(f)); return r;
}
__device__ __forceinline__ void mma_tf32(float c[4], const uint32_t a[4], const uint32_t b[2]) {
    asm volatile(
        "mma.sync.aligned.m16n8k8.row.col.f32.tf32.tf32.f32 "
        "{%0,%1,%2,%3}, {%4,%5,%6,%7}, {%8,%9}, {%0,%1,%2,%3};"
        : "+f"(c[0]), "+f"(c[1]), "+f"(c[2]), "+f"(c[3])
        : "r"(a[0]), "r"(a[1]), "r"(a[2]), "r"(a[3]), "r"(b[0]), "r"(b[1]));
}
__device__ __forceinline__ uint32_t smaddr(const void* p) {
    return (uint32_t)__cvta_generic_to_shared(p);
}
__device__ __forceinline__ void cp4(uint32_t dst, const void* src) {
    asm volatile("cp.async.ca.shared.global [%0], [%1], 4;" :: "r"(dst), "l"(src));
}
__device__ __forceinline__ void cp16(uint32_t dst, const void* src) {
    asm volatile("cp.async.cg.shared.global [%0], [%1], 16;" :: "r"(dst), "l"(src));
}
#define CP_COMMIT() asm volatile("cp.async.commit_group;" ::: "memory")
#define CP_WAIT2()  asm volatile("cp.async.wait_group 2;" ::: "memory")

// ---------------- FeatureWiseAffine ----------------
__global__ void affine_kernel(const float* __restrict__ temb,
                              const float* __restrict__ aw,
                              const float* __restrict__ ab,
                              float* __restrict__ gbsum) {
    int b = blockIdx.x;
    int c = threadIdx.x;
    __shared__ float t[192];
    t[c] = temb[b * 192 + c];
    __syncthreads();
    float s = ab[c] + ab[192 + c];
    const float* w1 = aw + c * 192;
    const float* w2 = aw + (192 + c) * 192;
    for (int e = 0; e < 192; ++e) s = fmaf(t[e], w1[e] + w2[e], s);
    gbsum[b * 192 + c] = 0.5f * s;
}

// ---------------- weight transposes ----------------
__global__ __launch_bounds__(256) void wt_transpose(const float* __restrict__ w,
                                                    float* __restrict__ o) {
    int i = blockIdx.x * 256 + threadIdx.x;
    if (i < CC * 1728) {
        int n = i / 1728;
        int k = i - n * 1728;
        int ci = k / 9;
        int tap = k - ci * 9;
        o[n * 1728 + tap * 192 + ci] = w[i];
    }
}
// out_w [192][16][3][3] -> [n][tap*16+ci], K padded to 160 (zeros untouched)
__global__ __launch_bounds__(256) void wt2_transpose(const float* __restrict__ w,
                                                     float* __restrict__ o) {
    int i = blockIdx.x * 256 + threadIdx.x;
    if (i < CC * 144) {
        int n = i / 144;
        int k = i - n * 144;
        int ci = k / 9;
        int tap = k - ci * 9;
        o[n * 160 + tap * 16 + ci] = w[i];
    }
}

// ---------------- GroupNorm stats ----------------
__global__ __launch_bounds__(256) void gn_stats(const float* __restrict__ in,
                                                float* __restrict__ mean,
                                                float* __restrict__ rstd) {
    int bg = blockIdx.x;
    const float* base = in + (long)bg * 13824;
    float s = 0.f, s2 = 0.f;
    for (int i = threadIdx.x; i < 13824; i += 256) {
        float v = base[i];
        s += v; s2 = fmaf(v, v, s2);
    }
    __shared__ float shs[8], shs2[8];
    int w = threadIdx.x >> 5, l = threadIdx.x & 31;
    s = warp_red(s); s2 = warp_red(s2);
    if (l == 0) { shs[w] = s; shs2[w] = s2; }
    __syncthreads();
    if (w == 0) {
        s  = (l < 8) ? shs[l]  : 0.f;
        s2 = (l < 8) ? shs2[l] : 0.f;
        s = warp_red(s); s2 = warp_red(s2);
        if (l == 0) {
            float m = s * (1.f / 13824.f);
            float var = s2 * (1.f / 13824.f) - m * m;
            mean[bg] = m;
            rstd[bg] = rsqrtf(var + 1e-5f);
        }
    }
}

// ---------------- GroupNorm apply + swish -> padded [b][c][50][50] ----------------
__global__ __launch_bounds__(256) void gn_apply_pad(const float* __restrict__ in,
                                                    const float* __restrict__ mean,
                                                    const float* __restrict__ rstd,
                                                    const float* __restrict__ w,
                                                    const float* __restrict__ bb,
                                                    float* __restrict__ outpad) {
    int idx = blockIdx.x * 256 + threadIdx.x;
    int bc = idx / SP;
    int sp = idx - bc * SP;
    int b = bc / CC;
    int c = bc - b * CC;
    int sidx = b * 32 + c / 6;
    float y = (in[idx] - mean[sidx]) * rstd[sidx] * w[c] + bb[c];
    y = y / (1.f + __expf(-y));
    int py = sp / 48, px = sp - py * 48;
    outpad[(size_t)bc * 2500 + (py + 1) * 50 + (px + 1)] = y;
}

// ---------------- mma.sync TF32 implicit-GEMM 3x3 conv (CIN=192), cp.async ----------
#define WST 36
#define ASZ (192 * WST)
#define BSZ (32 * 128)
#define STG (ASZ + BSZ)
template<int EPI>
__global__ __launch_bounds__(256) void conv_mma(const float* __restrict__ pad,
                                                const float* __restrict__ wt,
                                                const float* __restrict__ bias,
                                                const float* __restrict__ extra,
                                                float* __restrict__ out) {
    extern __shared__ uint32_t sm[];

    const int mtile = blockIdx.x;
    const int b = blockIdx.y;
    const int tid = threadIdx.x;
    const int wid = tid >> 5;
    const int lane = tid & 31;
    const int g = lane >> 2;
    const int t = lane & 3;
    const int wm = wid & 3;
    const int wn = wid >> 2;

    const int p = tid & 127;
    const int khalf = tid >> 7;
    const int pg = mtile * 128 + p;
    const int py = pg / 48;
    const int px = pg - py * 48;
    const float* padb = pad + (size_t)b * CC * 2500;

    auto stage = [&](int c) {
        uint32_t* buf = sm + (c & 3) * STG;
        const int tap = c / 6;
        const int ci0 = (c - tap * 6) * 32;
        const int dy = tap / 3;
        const int dx = tap - dy * 3;
        const float* bsrc = padb + (size_t)(ci0 + khalf * 16) * 2500
                          + (py + dy) * 50 + (px + dx);
        uint32_t* Bs = buf + ASZ;
        #pragma unroll
        for (int i = 0; i < 16; ++i) {
            int kk = khalf * 16 + i;
            cp4(smaddr(&Bs[kk * 128 + (p ^ ((kk & 3) * 8))]), bsrc + (size_t)i * 2500);
        }
        #pragma unroll
        for (int it = 0; it < 6; ++it) {
            int idx = it * 256 + tid;
            int n = idx >> 3;
            int kq = (idx & 7) * 4;
            cp16(smaddr(&buf[n * WST + kq]), wt + (size_t)n * 1728 + c * 32 + kq);
        }
    };

    stage(0); CP_COMMIT();
    stage(1); CP_COMMIT();
    stage(2); CP_COMMIT();

    float acc[3][8][4];
    #pragma unroll
    for (int i = 0; i < 3; ++i)
        #pragma unroll
        for (int j = 0; j < 8; ++j)
            #pragma unroll
            for (int q = 0; q < 4; ++q) acc[i][j][q] = 0.f;

    for (int c = 0; c < 54; ++c) {
        CP_WAIT2();
        __syncthreads();
        const uint32_t* Wp = sm + (c & 3) * STG;
        const uint32_t* Ip = Wp + ASZ;
        #pragma unroll
        for (int ks = 0; ks < 4; ++ks) {
            const int kk0 = ks * 8;
            uint32_t afr[3][4];
            #pragma unroll
            for (int i = 0; i < 3; ++i) {
                int row = wm * 48 + i * 16 + g;
                afr[i][0] = Wp[row * WST + kk0 + t];
                afr[i][1] = Wp[(row + 8) * WST + kk0 + t];
                afr[i][2] = Wp[row * WST + kk0 + t + 4];
                afr[i][3] = Wp[(row + 8) * WST + kk0 + t + 4];
            }
            uint32_t bfr[8][2];
            #pragma unroll
            for (int j = 0; j < 8; ++j) {
                int pp = wn * 64 + j * 8 + g;
                int ppx = pp ^ (t * 8);
                bfr[j][0] = Ip[(kk0 + t) * 128 + ppx];
                bfr[j][1] = Ip[(kk0 + t + 4) * 128 + ppx];
            }
            #pragma unroll
            for (int i = 0; i < 3; ++i)
                #pragma unroll
                for (int j = 0; j < 8; ++j)
                    mma_tf32(acc[i][j], afr[i], bfr[j]);
        }
        if (c + 3 < 54) stage(c + 3);
        CP_COMMIT();
    }

    #pragma unroll
    for (int i = 0; i < 3; ++i) {
        const int ch0 = wm * 48 + i * 16 + g;
        const int ch1 = ch0 + 8;
        const float bv0 = bias[ch0], bv1 = bias[ch1];
        float ga0 = 0.f, ga1 = 0.f;
        if (EPI == 0) { ga0 = extra[b * CC + ch0]; ga1 = extra[b * CC + ch1]; }
        #pragma unroll
        for (int j = 0; j < 8; ++j) {
            const int pos = mtile * 128 + wn * 64 + j * 8 + 2 * t;
            long idx0 = ((long)b * CC + ch0) * SP + pos;
            long idx1 = ((long)b * CC + ch1) * SP + pos;
            float y0 = acc[i][j][0] + bv0;
            float y1 = acc[i][j][1] + bv0;
            float y2 = acc[i][j][2] + bv1;
            float y3 = acc[i][j][3] + bv1;
            if (EPI == 0) {
                y0 += ga0 * y0 + ga0; y1 += ga0 * y1 + ga0;
                y2 += ga1 * y2 + ga1; y3 += ga1 * y3 + ga1;
            } else {
                float2 e0 = *(const float2*)(extra + idx0);
                float2 e1 = *(const float2*)(extra + idx1);
                y0 += e0.x; y1 += e0.y; y2 += e1.x; y3 += e1.y;
            }
            *(float2*)(out + idx0) = make_float2(y0, y1);
            *(float2*)(out + idx1) = make_float2(y2, y3);
        }
    }
}

// ---------------- out conv: CIN=16 (K padded to 160), same pipeline ----------------
__global__ __launch_bounds__(256) void conv_mma16(const float* __restrict__ pad2,
                                                  const float* __restrict__ wt,
                                                  const float* __restrict__ bias,
                                                  const float* __restrict__ extra,
                                                  float* __restrict__ out) {
    extern __shared__ uint32_t sm[];

    const int mtile = blockIdx.x;
    const int b = blockIdx.y;
    const int tid = threadIdx.x;
    const int wid = tid >> 5;
    const int lane = tid & 31;
    const int g = lane >> 2;
    const int t = lane & 3;
    const int wm = wid & 3;
    const int wn = wid >> 2;

    const int p = tid & 127;
    const int khalf = tid >> 7;
    const int pg = mtile * 128 + p;
    const int py = pg / 48;
    const int px = pg - py * 48;
    const float* padb = pad2 + (size_t)b * 16 * 2600;

    auto stage = [&](int c) {
        uint32_t* buf = sm + (c & 3) * STG;
        const int tap = 2 * c + khalf;           // kk = khalf*16+i -> tap, ci=i
        const int dy = tap / 3;
        const int dx = tap - dy * 3;
        const float* bsrc = padb + (py + dy) * 50 + (px + dx);
        uint32_t* Bs = buf + ASZ;
        #pragma unroll
        for (int i = 0; i < 16; ++i) {
            int kk = khalf * 16 + i;
            cp4(smaddr(&Bs[kk * 128 + (p ^ ((kk & 3) * 8))]), bsrc + (size_t)i * 2600);
        }
        #pragma unroll
        for (int it = 0; it < 6; ++it) {
            int idx = it * 256 + tid;
            int n = idx >> 3;
            int kq = (idx & 7) * 4;
            cp16(smaddr(&buf[n * WST + kq]), wt + (size_t)n * 160 + c * 32 + kq);
        }
    };

    stage(0); CP_COMMIT();
    stage(1); CP_COMMIT();
    stage(2); CP_COMMIT();

    float acc[3][8][4];
    #pragma unroll
    for (int i = 0; i < 3; ++i)
        #pragma unroll
        for (int j = 0; j < 8; ++j)
            #pragma unroll
            for (int q = 0; q < 4; ++q) acc[i][j][q] = 0.f;

    for (int c = 0; c < 5; ++c) {
        CP_WAIT2();
        __syncthreads();
        const uint32_t* Wp = sm + (c & 3) * STG;
        const uint32_t* Ip = Wp + ASZ;
        #pragma unroll
        for (int ks = 0; ks < 4; ++ks) {
            const int kk0 = ks * 8;
            uint32_t afr[3][4];
            #pragma unroll
            for (int i = 0; i < 3; ++i) {
                int row = wm * 48 + i * 16 + g;
                afr[i][0] = Wp[row * WST + kk0 + t];
                afr[i][1] = Wp[(row + 8) * WST + kk0 + t];
                afr[i][2] = Wp[row * WST + kk0 + t + 4];
                afr[i][3] = Wp[(row + 8) * WST + kk0 + t + 4];
            }
            uint32_t bfr[8][2];
            #pragma unroll
            for (int j = 0; j < 8; ++j) {
                int pp = wn * 64 + j * 8 + g;
                int ppx = pp ^ (t * 8);
                bfr[j][0] = Ip[(kk0 + t) * 128 + ppx];
                bfr[j][1] = Ip[(kk0 + t + 4) * 128 + ppx];
            }
            #pragma unroll
            for (int i = 0; i < 3; ++i)
                #pragma unroll
                for (int j = 0; j < 8; ++j)
                    mma_tf32(acc[i][j], afr[i], bfr[j]);
        }
        if (c + 3 < 5) stage(c + 3);
        CP_COMMIT();
    }

    #pragma unroll
    for (int i = 0; i < 3; ++i) {
        const int ch0 = wm * 48 + i * 16 + g;
        const int ch1 = ch0 + 8;
        const float bv0 = bias[ch0], bv1 = bias[ch1];
        #pragma unroll
        for (int j = 0; j < 8; ++j) {
            const int pos = mtile * 128 + wn * 64 + j * 8 + 2 * t;
            long idx0 = ((long)b * CC + ch0) * SP + pos;
            long idx1 = ((long)b * CC + ch1) * SP + pos;
            float2 e0 = *(const float2*)(extra + idx0);
            float2 e1 = *(const float2*)(extra + idx1);
            *(float2*)(out + idx0) = make_float2(acc[i][j][0] + bv0 + e0.x,
                                                 acc[i][j][1] + bv0 + e0.y);
            *(float2*)(out + idx1) = make_float2(acc[i][j][2] + bv1 + e1.x,
                                                 acc[i][j][3] + bv1 + e1.y);
        }
    }
}

// ---------------- 1x1 conv ----------------
template<int CO>
__global__ __launch_bounds__(256) void conv1x1(const float* __restrict__ in,
                                               const float* __restrict__ wgt,
                                               float* __restrict__ out) {
    const int b = blockIdx.y;
    const int p0 = blockIdx.x * 256;
    const int tid = threadIdx.x;
    __shared__ float s_w[CO * 192];
    __shared__ float s_x[16 * 256];
    for (int i = tid; i < CO * 192; i += 256) s_w[i] = wgt[i];
    float acc[CO];
    #pragma unroll
    for (int co = 0; co < CO; ++co) acc[co] = 0.f;

    for (int c0 = 0; c0 < 192; c0 += 16) {
        __syncthreads();
        for (int i = tid; i < 16 * 256; i += 256) {
            int ci = i >> 8;
            int pp = i & 255;
            s_x[i] = in[((long)b * 192 + c0 + ci) * SP + p0 + pp];
        }
        __syncthreads();
        for (int ci = 0; ci < 16; ++ci) {
            float xv = s_x[ci * 256 + tid];
            #pragma unroll
            for (int co = 0; co < CO; ++co)
                acc[co] = fmaf(s_w[co * 192 + c0 + ci], xv, acc[co]);
        }
    }
    #pragma unroll
    for (int co = 0; co < CO; ++co)
        out[((long)b * CO + co) * SP + p0 + tid] = acc[co];
}

// ---------------- MMA flash attention -> padded [b][16][52][50] ----------------
// Each warp: 16 queries x full key range. S = (0.25 Q) K^T via tf32 mma; online
// softmax in regs; P.V via c-frag->a-frag permutation with row-permuted V smem.
__global__ __launch_bounds__(256) void attn_mma(const float* __restrict__ q,
                                                const float* __restrict__ kv,
                                                float* __restrict__ pad2) {
    const int b = blockIdx.y;
    const int mtile = blockIdx.x;
    const int q0 = mtile * 128;
    const int tid = threadIdx.x;
    const int wid = tid >> 5;
    const int lane = tid & 31;
    const int g = lane >> 2;
    const int t = lane & 3;

    __shared__ float k_s[16 * 136];
    __shared__ float v_s[128 * 24];

    // Q fragments (scaled by attention scale, tf32)
    uint32_t qa[2][4];
    #pragma unroll
    for (int kd = 0; kd < 2; ++kd)
        #pragma unroll
        for (int j = 0; j < 4; ++j) {
            int row = wid * 16 + g + (j & 1) * 8;
            int d = kd * 8 + t + (j >> 1) * 4;
            float v = q[((long)b * 16 + d) * SP + q0 + row] * 0.25f;
            qa[kd][j] = to_tf32(v);
        }

    float m[2] = { -3.4e38f, -3.4e38f };
    float l[2] = { 0.f, 0.f };
    float acc_o[2][4];
    #pragma unroll
    for (int dn = 0; dn < 2; ++dn)
        #pragma unroll
        for (int j = 0; j < 4; ++j) acc_o[dn][j] = 0.f;

    const long kvb = (long)b * 32 * SP;
    for (int kb = 0; kb < 18; ++kb) {
        __syncthreads();
        const int key0 = kb * 128;
        // stage K d-major [16][136]
        #pragma unroll
        for (int it = 0; it < 8; ++it) {
            int idx = it * 256 + tid;
            int c = idx >> 7;
            int key = idx & 127;
            k_s[c * 136 + key] =
                __uint_as_float(to_tf32(kv[kvb + (long)c * SP + key0 + key]));
        }
        // stage V row-permuted [128][24]
        #pragma unroll
        for (int it = 0; it < 8; ++it) {
            int idx = it * 256 + tid;
            int d = idx >> 7;
            int key = idx & 127;
            int kp = key & 7;
            int kap = (kp & 1) ? (kp >> 1) + 4 : (kp >> 1);
            int slot = (key & ~7) | kap;
            v_s[slot * 24 + d] =
                __uint_as_float(to_tf32(kv[kvb + (long)(16 + d) * SP + key0 + key]));
        }
        __syncthreads();

        // S = Q K^T
        float s_fr[16][4];
        #pragma unroll
        for (int nt = 0; nt < 16; ++nt) {
            float c4[4] = { 0.f, 0.f, 0.f, 0.f };
            #pragma unroll
            for (int kd = 0; kd < 2; ++kd) {
                uint32_t bfr[2];
                bfr[0] = __float_as_uint(k_s[(kd * 8 + t) * 136 + nt * 8 + g]);
                bfr[1] = __float_as_uint(k_s[(kd * 8 + t + 4) * 136 + nt * 8 + g]);
                mma_tf32(c4, qa[kd], bfr);
            }
            s_fr[nt][0] = c4[0]; s_fr[nt][1] = c4[1];
            s_fr[nt][2] = c4[2]; s_fr[nt][3] = c4[3];
        }

        // online softmax per row (r=0: c0/c1; r=1: c2/c3)
        #pragma unroll
        for (int r = 0; r < 2; ++r) {
            float vm = -3.4e38f;
            #pragma unroll
            for (int nt = 0; nt < 16; ++nt)
                vm = fmaxf(vm, fmaxf(s_fr[nt][r * 2], s_fr[nt][r * 2 + 1]));
            vm = fmaxf(vm, __shfl_xor_sync(0xffffffffu, vm, 1));
            vm = fmaxf(vm, __shfl_xor_sync(0xffffffffu, vm, 2));
            float mn = fmaxf(m[r], vm);
            float corr = __expf(m[r] - mn);
            m[r] = mn;
            float ls = 0.f;
            #pragma unroll
            for (int nt = 0; nt < 16; ++nt) {
                float e0 = __expf(s_fr[nt][r * 2] - mn);
                float e1 = __expf(s_fr[nt][r * 2 + 1] - mn);
                s_fr[nt][r * 2] = e0;
                s_fr[nt][r * 2 + 1] = e1;
                ls += e0 + e1;
            }
            ls += __shfl_xor_sync(0xffffffffu, ls, 1);
            ls += __shfl_xor_sync(0xffffffffu, ls, 2);
            l[r] = l[r] * corr + ls;
            #pragma unroll
            for (int dn = 0; dn < 2; ++dn) {
                acc_o[dn][r * 2] *= corr;
                acc_o[dn][r * 2 + 1] *= corr;
            }
        }

        // O += P V (c-frag -> a-frag permutation; V rows pre-permuted)
        #pragma unroll
        for (int nt = 0; nt < 16; ++nt) {
            uint32_t pa[4];
            pa[0] = __float_as_uint(s_fr[nt][0]);
            pa[1] = __float_as_uint(s_fr[nt][2]);
            pa[2] = __float_as_uint(s_fr[nt][1]);
            pa[3] = __float_as_uint(s_fr[nt][3]);
            #pragma unroll
            for (int dn = 0; dn < 2; ++dn) {
                uint32_t bfr[2];
                bfr[0] = __float_as_uint(v_s[(nt * 8 + t) * 24 + dn * 8 + g]);
                bfr[1] = __float_as_uint(v_s[(nt * 8 + t + 4) * 24 + dn * 8 + g]);
                mma_tf32(acc_o[dn], pa, bfr);
            }
        }
    }

    // write normalized output into padded [b][16][52][50]
    #pragma unroll
    for (int r = 0; r < 2; ++r) {
        float inv = 1.f / l[r];
        int pos = q0 + wid * 16 + g + r * 8;
        int py = pos / 48, px = pos - py * 48;
        #pragma unroll
        for (int dn = 0; dn < 2; ++dn)
            #pragma unroll
            for (int cc2 = 0; cc2 < 2; ++cc2) {
                int d = dn * 8 + 2 * t + cc2;
                pad2[((size_t)b * 16 + d) * 2600 + (py + 1) * 50 + (px + 1)] =
                    acc_o[dn][r * 2 + cc2] * inv;
            }
    }
}

// ---------------- launcher ----------------
extern "C" void kernel_launch(void* const* d_in, const int* in_sizes, int n_in,
                              void* d_out, int out_size) {
    const float* x       = (const float*)d_in[0];
    const float* xe      = (const float*)d_in[1];
    const float* temb    = (const float*)d_in[2];
    const float* gn1_w   = (const float*)d_in[3];
    const float* gn1_b   = (const float*)d_in[4];
    const float* conv1_w = (const float*)d_in[5];
    const float* conv1_b = (const float*)d_in[6];
    const float* aff_w   = (const float*)d_in[7];
    const float* aff_b   = (const float*)d_in[8];
    const float* gn2_w   = (const float*)d_in[9];
    const float* gn2_b   = (const float*)d_in[10];
    const float* conv2_w = (const float*)d_in[11];
    const float* conv2_b = (const float*)d_in[12];
    const float* q_w     = (const float*)d_in[13];
    const float* kv_w    = (const float*)d_in[14];
    const float* out_w   = (const float*)d_in[15];
    const float* out_b   = (const float*)d_in[16];

    float *padp, *pad2p, *wtp, *wtBp, *wt2p, *h, *xres, *qb, *kvb, *mean, *rstd, *gbsum;
    cudaGetSymbolAddress((void**)&padp,  g_pad);
    cudaGetSymbolAddress((void**)&pad2p, g_pad2);
    cudaGetSymbolAddress((void**)&wtp,   g_wt);
    cudaGetSymbolAddress((void**)&wtBp,  g_wtB);
    cudaGetSymbolAddress((void**)&wt2p,  g_wt2);
    cudaGetSymbolAddress((void**)&h,     g_h);
    cudaGetSymbolAddress((void**)&xres,  g_xres);
    cudaGetSymbolAddress((void**)&qb,    g_q);
    cudaGetSymbolAddress((void**)&kvb,   g_kv);
    cudaGetSymbolAddress((void**)&mean,  g_mean);
    cudaGetSymbolAddress((void**)&rstd,  g_rstd);
    cudaGetSymbolAddress((void**)&gbsum, g_gbsum);

    const int DSM = 4 * STG * 4;
    cudaFuncSetAttribute(conv_mma<0>, cudaFuncAttributeMaxDynamicSharedMemorySize, DSM);
    cudaFuncSetAttribute(conv_mma<1>, cudaFuncAttributeMaxDynamicSharedMemorySize, DSM);
    cudaFuncSetAttribute(conv_mma16, cudaFuncAttributeMaxDynamicSharedMemorySize, DSM);

    // launches 1..5 (so #6 = conv_mma<0> for ncu -s 5 -c 1)
    affine_kernel<<<BB, 192>>>(temb, aff_w, aff_b, gbsum);                    // 1
    gn_stats<<<BB * 32, 256>>>(x, mean, rstd);                                // 2
    gn_apply_pad<<<TOTAL / 256, 256>>>(x, mean, rstd, gn1_w, gn1_b, padp);    // 3
    wt_transpose<<<1296, 256>>>(conv1_w, wtp);                                // 4
    wt_transpose<<<1296, 256>>>(conv2_w, wtBp);                               // 5
    conv_mma<0><<<dim3(18, BB), 256, DSM>>>(padp, wtp, conv1_b, gbsum, h);    // 6

    gn_stats<<<BB * 32, 256>>>(h, mean, rstd);
    gn_apply_pad<<<TOTAL / 256, 256>>>(h, mean, rstd, gn2_w, gn2_b, padp);
    conv_mma<1><<<dim3(18, BB), 256, DSM>>>(padp, wtBp, conv2_b, x, xres);

    conv1x1<16><<<dim3(9, BB), 256>>>(xres, q_w, qb);
    conv1x1<32><<<dim3(9, BB), 256>>>(xe, kv_w, kvb);
    wt2_transpose<<<108, 256>>>(out_w, wt2p);
    attn_mma<<<dim3(18, BB), 256>>>(qb, kvb, pad2p);
    conv_mma16<<<dim3(18, BB), 256, DSM>>>(pad2p, wt2p, out_b, xres, (float*)d_out);
}

// round 8
// speedup vs baseline: 2.8134x; 1.0131x over previous
#include <cuda_runtime.h>
#include <cstdint>
#include <math.h>

#define HH 48
#define WW 48
#define SP 2304
#define CC 192
#define BB 8
#define TOTAL 3538944

typedef unsigned long long u64;

// ---------------- scratch ----------------
__device__ float g_pad[BB*CC*2500];    // zero-bordered [b][c][50][50]
__device__ float g_pad2[BB*16*2600];   // zero-bordered [b][c][52][50] (attn out)
__device__ float g_wt[CC*1728];        // conv1 weights tap-major
__device__ float g_wtB[CC*1728];       // conv2 weights tap-major
__device__ float g_wt2[CC*160];        // out conv weights tap-major, K padded to 160
__device__ float g_h[TOTAL];
__device__ float g_xres[TOTAL];
__device__ float g_q[BB*16*SP];
__device__ float g_kv[BB*32*SP];
__device__ float g_mean[BB*32];
__device__ float g_rstd[BB*32];
__device__ float g_gbsum[BB*CC];

// ---------------- helpers ----------------
__device__ __forceinline__ float warp_red(float v) {
    #pragma unroll
    for (int o = 16; o > 0; o >>= 1) v += __shfl_down_sync(0xffffffffu, v, o);
    return v;
}
__device__ __forceinline__ uint32_t to_tf32(float f) {
    uint32_t r; asm("cvt.rna.tf32.f32 %0, %1;" : "=r"(r) : "f"(f)); return r;
}
__device__ __forceinline__ void mma_tf32(float c[4], const uint32_t a[4], const uint32_t b[2]) {
    asm volatile(
        "mma.sync.aligned.m16n8k8.row.col.f32.tf32.tf32.f32 "
        "{%0,%1,%2,%3}, {%4,%5,%6,%7}, {%8,%9}, {%0,%1,%2,%3};"
        : "+f"(c[0]), "+f"(c[1]), "+f"(c[2]), "+f"(c[3])
        : "r"(a[0]), "r"(a[1]), "r"(a[2]), "r"(a[3]), "r"(b[0]), "r"(b[1]));
}
__device__ __forceinline__ void ldsm_x4(uint32_t r[4], uint32_t addr) {
    asm volatile("ldmatrix.sync.aligned.m8n8.x4.shared.b16 {%0,%1,%2,%3}, [%4];"
        : "=r"(r[0]), "=r"(r[1]), "=r"(r[2]), "=r"(r[3]) : "r"(addr));
}
__device__ __forceinline__ uint32_t smaddr(const void* p) {
    return (uint32_t)__cvta_generic_to_shared(p);
}
__device__ __forceinline__ void cp4(uint32_t dst, const void* src) {
    asm volatile("cp.async.ca.shared.global [%0], [%1], 4;" :: "r"(dst), "l"(src));
}
__device__ __forceinline__ void cp16(uint32_t dst, const void* src) {
    asm volatile("cp.async.cg.shared.global [%0], [%1], 16;" :: "r"(dst), "l"(src));
}
#define CP_COMMIT() asm volatile("cp.async.commit_group;" ::: "memory")
#define CP_WAIT2()  asm volatile("cp.async.wait_group 2;" ::: "memory")

// ---------------- prep: affine + all 3 weight transposes in one launch ----------------
__global__ __launch_bounds__(256) void prep_kernel(const float* __restrict__ temb,
                                                   const float* __restrict__ aw,
                                                   const float* __restrict__ ab,
                                                   float* __restrict__ gbsum,
                                                   const float* __restrict__ w1,
                                                   const float* __restrict__ w2,
                                                   const float* __restrict__ w3,
                                                   float* __restrict__ o1,
                                                   float* __restrict__ o2,
                                                   float* __restrict__ o3) {
    int bx = blockIdx.x;
    int tid = threadIdx.x;
    if (bx < 8) {
        // FeatureWiseAffine for batch bx
        if (tid < 192) {
            __shared__ float t[192];
            t[tid] = temb[bx * 192 + tid];
            __syncwarp();
            __syncthreads();
            float s = ab[tid] + ab[192 + tid];
            const float* wa = aw + tid * 192;
            const float* wb = aw + (192 + tid) * 192;
            for (int e = 0; e < 192; ++e) s = fmaf(t[e], wa[e] + wb[e], s);
            gbsum[bx * 192 + tid] = 0.5f * s;
        } else {
            __syncthreads();
        }
    } else if (bx < 8 + 1296) {
        int i = (bx - 8) * 256 + tid;
        if (i < CC * 1728) {
            int n = i / 1728;
            int k = i - n * 1728;
            int ci = k / 9;
            int tap = k - ci * 9;
            o1[n * 1728 + tap * 192 + ci] = w1[i];
        }
    } else if (bx < 8 + 2592) {
        int i = (bx - 8 - 1296) * 256 + tid;
        if (i < CC * 1728) {
            int n = i / 1728;
            int k = i - n * 1728;
            int ci = k / 9;
            int tap = k - ci * 9;
            o2[n * 1728 + tap * 192 + ci] = w2[i];
        }
    } else {
        int i = (bx - 8 - 2592) * 256 + tid;
        if (i < CC * 144) {
            int n = i / 144;
            int k = i - n * 144;
            int ci = k / 9;
            int tap = k - ci * 9;
            o3[n * 160 + tap * 16 + ci] = w3[i];
        }
    }
}

// ---------------- GroupNorm stats ----------------
__global__ __launch_bounds__(256) void gn_stats(const float* __restrict__ in,
                                                float* __restrict__ mean,
                                                float* __restrict__ rstd) {
    int bg = blockIdx.x;
    const float* base = in + (long)bg * 13824;
    float s = 0.f, s2 = 0.f;
    for (int i = threadIdx.x; i < 13824; i += 256) {
        float v = base[i];
        s += v; s2 = fmaf(v, v, s2);
    }
    __shared__ float shs[8], shs2[8];
    int w = threadIdx.x >> 5, l = threadIdx.x & 31;
    s = warp_red(s); s2 = warp_red(s2);
    if (l == 0) { shs[w] = s; shs2[w] = s2; }
    __syncthreads();
    if (w == 0) {
        s  = (l < 8) ? shs[l]  : 0.f;
        s2 = (l < 8) ? shs2[l] : 0.f;
        s = warp_red(s); s2 = warp_red(s2);
        if (l == 0) {
            float m = s * (1.f / 13824.f);
            float var = s2 * (1.f / 13824.f) - m * m;
            mean[bg] = m;
            rstd[bg] = rsqrtf(var + 1e-5f);
        }
    }
}

// ---------------- GroupNorm apply + swish -> padded [b][c][50][50] ----------------
__global__ __launch_bounds__(256) void gn_apply_pad(const float* __restrict__ in,
                                                    const float* __restrict__ mean,
                                                    const float* __restrict__ rstd,
                                                    const float* __restrict__ w,
                                                    const float* __restrict__ bb,
                                                    float* __restrict__ outpad) {
    int idx = blockIdx.x * 256 + threadIdx.x;
    int bc = idx / SP;
    int sp = idx - bc * SP;
    int b = bc / CC;
    int c = bc - b * CC;
    int sidx = b * 32 + c / 6;
    float y = (in[idx] - mean[sidx]) * rstd[sidx] * w[c] + bb[c];
    y = y / (1.f + __expf(-y));
    int py = sp / 48, px = sp - py * 48;
    outpad[(size_t)bc * 2500 + (py + 1) * 50 + (px + 1)] = y;
}

// ---------------- direct-shift TF32 mma conv (CIN=192, OC=192) --------------------
// Tile: 8 rows x 16 cols of output positions per CTA. Input chunk = 16 channels,
// staged once as [16][10x18] halo tile (stride 184); B fragments read with the
// (dy,dx) shift folded into the LDS address. Weights: 4-stage ring [192][16] per
// (chunk,tap), stride 20, A-frags via ldmatrix.x4.
#define WROW 20
#define WBUFSZ (192 * WROW)       // 3840 floats per weight stage
#define IBUFSZ (16 * 184)         // 2944 floats per input buffer
#define IOFF (4 * WBUFSZ)         // input buffers after weight ring
template<int EPI>
__global__ __launch_bounds__(256) void conv_mma(const float* __restrict__ pad,
                                                const float* __restrict__ wt,
                                                const float* __restrict__ bias,
                                                const float* __restrict__ extra,
                                                float* __restrict__ out) {
    extern __shared__ float sm[];

    const int mtile = blockIdx.x;       // 0..17
    const int b = blockIdx.y;
    const int tr = mtile / 3;           // row-tile 0..5 (8 rows)
    const int tcl = mtile - tr * 3;     // col-tile 0..2 (16 cols)
    const int tid = threadIdx.x;
    const int wid = tid >> 5;
    const int lane = tid & 31;
    const int g = lane >> 2;
    const int t = lane & 3;
    const int wm = wid & 3;             // 4 M tiles of 48 channels
    const int wn = wid >> 2;            // 2 N tiles of 64 positions

    const float* padb = pad + (size_t)b * CC * 2500;

    // ldmatrix per-lane address offset (bytes) within a weight stage
    const uint32_t lane_a_off =
        ((uint32_t)((wm * 48 + (lane & 15)) * WROW + ((lane >> 4) << 2))) << 2;

    auto stage = [&](int s) {
        int c = s / 9;
        int tap = s - c * 9;
        float* wbuf = sm + (s & 3) * WBUFSZ;
        #pragma unroll
        for (int it = 0; it < 3; ++it) {
            int idx = it * 256 + tid;
            int n = idx >> 2;
            int kq = (idx & 3) * 4;
            cp16(smaddr(&wbuf[n * WROW + kq]),
                 wt + (size_t)n * 1728 + tap * 192 + c * 16 + kq);
        }
        if (tap == 0) {
            float* ibuf = sm + IOFF + (c & 1) * IBUFSZ;
            #pragma unroll
            for (int it = 0; it < 12; ++it) {
                int idx = it * 256 + tid;
                if (idx < 2880) {
                    int ci = idx / 180;
                    int rem = idx - ci * 180;
                    int rr = rem / 18;
                    int cc2 = rem - rr * 18;
                    cp4(smaddr(&ibuf[ci * 184 + rr * 18 + cc2]),
                        padb + (size_t)(c * 16 + ci) * 2500
                             + (tr * 8 + rr) * 50 + tcl * 16 + cc2);
                }
            }
        }
    };

    stage(0); CP_COMMIT();
    stage(1); CP_COMMIT();
    stage(2); CP_COMMIT();

    float acc[3][8][4];
    #pragma unroll
    for (int i = 0; i < 3; ++i)
        #pragma unroll
        for (int j = 0; j < 8; ++j)
            #pragma unroll
            for (int q = 0; q < 4; ++q) acc[i][j][q] = 0.f;

    for (int s = 0; s < 108; ++s) {
        CP_WAIT2();
        __syncthreads();
        const int c = s / 9;
        const int tap = s - c * 9;
        const int dy = tap / 3;
        const int dx = tap - dy * 3;
        const uint32_t wb_addr = smaddr(sm + (s & 3) * WBUFSZ) + lane_a_off;
        const float* ib = sm + IOFF + (c & 1) * IBUFSZ
                        + dy * 18 + dx + t * 184 + wn * 72 + g;
        #pragma unroll
        for (int ks = 0; ks < 2; ++ks) {
            const float* ibk = ib + ks * (8 * 184);
            uint32_t afr[3][4];
            #pragma unroll
            for (int i = 0; i < 3; ++i)
                ldsm_x4(afr[i], wb_addr + i * (16 * WROW * 4) + ks * 32);
            uint32_t bfr[8][2];
            #pragma unroll
            for (int j = 0; j < 8; ++j) {
                const float* a = ibk + (j >> 1) * 18 + (j & 1) * 8;
                bfr[j][0] = *(const uint32_t*)a;
                bfr[j][1] = *(const uint32_t*)(a + 4 * 184);
            }
            #pragma unroll
            for (int i = 0; i < 3; ++i)
                #pragma unroll
                for (int j = 0; j < 8; ++j)
                    mma_tf32(acc[i][j], afr[i], bfr[j]);
        }
        if (s + 3 < 108) stage(s + 3);
        CP_COMMIT();
    }

    // epilogue: tile position n -> (y,x); coalesced float2 stores
    #pragma unroll
    for (int i = 0; i < 3; ++i) {
        const int ch0 = wm * 48 + i * 16 + g;
        const int ch1 = ch0 + 8;
        const float bv0 = bias[ch0], bv1 = bias[ch1];
        float ga0 = 0.f, ga1 = 0.f;
        if (EPI == 0) { ga0 = extra[b * CC + ch0]; ga1 = extra[b * CC + ch1]; }
        #pragma unroll
        for (int j = 0; j < 8; ++j) {
            const int n = wn * 64 + j * 8 + 2 * t;
            const int yy = tr * 8 + (n >> 4);
            const int xx = tcl * 16 + (n & 15);
            long idx0 = (((long)b * CC + ch0) * 48 + yy) * 48 + xx;
            long idx1 = (((long)b * CC + ch1) * 48 + yy) * 48 + xx;
            float y0 = acc[i][j][0] + bv0;
            float y1 = acc[i][j][1] + bv0;
            float y2 = acc[i][j][2] + bv1;
            float y3 = acc[i][j][3] + bv1;
            if (EPI == 0) {
                y0 += ga0 * y0 + ga0; y1 += ga0 * y1 + ga0;
                y2 += ga1 * y2 + ga1; y3 += ga1 * y3 + ga1;
            } else {
                float2 e0 = *(const float2*)(extra + idx0);
                float2 e1 = *(const float2*)(extra + idx1);
                y0 += e0.x; y1 += e0.y; y2 += e1.x; y3 += e1.y;
            }
            *(float2*)(out + idx0) = make_float2(y0, y1);
            *(float2*)(out + idx1) = make_float2(y2, y3);
        }
    }
}

// ---------------- out conv: CIN=16 (K padded to 160), im2col pipeline ----------------
#define WST 36
#define ASZ (192 * WST)
#define BSZ (32 * 128)
#define STG (ASZ + BSZ)
__global__ __launch_bounds__(256) void conv_mma16(const float* __restrict__ pad2,
                                                  const float* __restrict__ wt,
                                                  const float* __restrict__ bias,
                                                  const float* __restrict__ extra,
                                                  float* __restrict__ out) {
    extern __shared__ float smf[];
    uint32_t* sm = (uint32_t*)smf;

    const int mtile = blockIdx.x;
    const int b = blockIdx.y;
    const int tid = threadIdx.x;
    const int wid = tid >> 5;
    const int lane = tid & 31;
    const int g = lane >> 2;
    const int t = lane & 3;
    const int wm = wid & 3;
    const int wn = wid >> 2;

    const int p = tid & 127;
    const int khalf = tid >> 7;
    const int pg = mtile * 128 + p;
    const int py = pg / 48;
    const int px = pg - py * 48;
    const float* padb = pad2 + (size_t)b * 16 * 2600;

    auto stage = [&](int c) {
        uint32_t* buf = sm + (c & 3) * STG;
        const int tap = 2 * c + khalf;
        const int dy = tap / 3;
        const int dx = tap - dy * 3;
        const float* bsrc = padb + (py + dy) * 50 + (px + dx);
        uint32_t* Bs = buf + ASZ;
        #pragma unroll
        for (int i = 0; i < 16; ++i) {
            int kk = khalf * 16 + i;
            cp4(smaddr(&Bs[kk * 128 + (p ^ ((kk & 3) * 8))]), bsrc + (size_t)i * 2600);
        }
        #pragma unroll
        for (int it = 0; it < 6; ++it) {
            int idx = it * 256 + tid;
            int n = idx >> 3;
            int kq = (idx & 7) * 4;
            cp16(smaddr(&buf[n * WST + kq]), wt + (size_t)n * 160 + c * 32 + kq);
        }
    };

    stage(0); CP_COMMIT();
    stage(1); CP_COMMIT();
    stage(2); CP_COMMIT();

    float acc[3][8][4];
    #pragma unroll
    for (int i = 0; i < 3; ++i)
        #pragma unroll
        for (int j = 0; j < 8; ++j)
            #pragma unroll
            for (int q = 0; q < 4; ++q) acc[i][j][q] = 0.f;

    for (int c = 0; c < 5; ++c) {
        CP_WAIT2();
        __syncthreads();
        const uint32_t* Wp = sm + (c & 3) * STG;
        const uint32_t* Ip = Wp + ASZ;
        #pragma unroll
        for (int ks = 0; ks < 4; ++ks) {
            const int kk0 = ks * 8;
            uint32_t afr[3][4];
            #pragma unroll
            for (int i = 0; i < 3; ++i) {
                int row = wm * 48 + i * 16 + g;
                afr[i][0] = Wp[row * WST + kk0 + t];
                afr[i][1] = Wp[(row + 8) * WST + kk0 + t];
                afr[i][2] = Wp[row * WST + kk0 + t + 4];
                afr[i][3] = Wp[(row + 8) * WST + kk0 + t + 4];
            }
            uint32_t bfr[8][2];
            #pragma unroll
            for (int j = 0; j < 8; ++j) {
                int pp = wn * 64 + j * 8 + g;
                int ppx = pp ^ (t * 8);
                bfr[j][0] = Ip[(kk0 + t) * 128 + ppx];
                bfr[j][1] = Ip[(kk0 + t + 4) * 128 + ppx];
            }
            #pragma unroll
            for (int i = 0; i < 3; ++i)
                #pragma unroll
                for (int j = 0; j < 8; ++j)
                    mma_tf32(acc[i][j], afr[i], bfr[j]);
        }
        if (c + 3 < 5) stage(c + 3);
        CP_COMMIT();
    }

    #pragma unroll
    for (int i = 0; i < 3; ++i) {
        const int ch0 = wm * 48 + i * 16 + g;
        const int ch1 = ch0 + 8;
        const float bv0 = bias[ch0], bv1 = bias[ch1];
        #pragma unroll
        for (int j = 0; j < 8; ++j) {
            const int pos = mtile * 128 + wn * 64 + j * 8 + 2 * t;
            long idx0 = ((long)b * CC + ch0) * SP + pos;
            long idx1 = ((long)b * CC + ch1) * SP + pos;
            float2 e0 = *(const float2*)(extra + idx0);
            float2 e1 = *(const float2*)(extra + idx1);
            *(float2*)(out + idx0) = make_float2(acc[i][j][0] + bv0 + e0.x,
                                                 acc[i][j][1] + bv0 + e0.y);
            *(float2*)(out + idx1) = make_float2(acc[i][j][2] + bv1 + e1.x,
                                                 acc[i][j][3] + bv1 + e1.y);
        }
    }
}

// ---------------- 1x1 conv ----------------
template<int CO>
__global__ __launch_bounds__(256) void conv1x1(const float* __restrict__ in,
                                               const float* __restrict__ wgt,
                                               float* __restrict__ out) {
    const int b = blockIdx.y;
    const int p0 = blockIdx.x * 256;
    const int tid = threadIdx.x;
    __shared__ float s_w[CO * 192];
    __shared__ float s_x[16 * 256];
    for (int i = tid; i < CO * 192; i += 256) s_w[i] = wgt[i];
    float acc[CO];
    #pragma unroll
    for (int co = 0; co < CO; ++co) acc[co] = 0.f;

    for (int c0 = 0; c0 < 192; c0 += 16) {
        __syncthreads();
        for (int i = tid; i < 16 * 256; i += 256) {
            int ci = i >> 8;
            int pp = i & 255;
            s_x[i] = in[((long)b * 192 + c0 + ci) * SP + p0 + pp];
        }
        __syncthreads();
        for (int ci = 0; ci < 16; ++ci) {
            float xv = s_x[ci * 256 + tid];
            #pragma unroll
            for (int co = 0; co < CO; ++co)
                acc[co] = fmaf(s_w[co * 192 + c0 + ci], xv, acc[co]);
        }
    }
    #pragma unroll
    for (int co = 0; co < CO; ++co)
        out[((long)b * CO + co) * SP + p0 + tid] = acc[co];
}

// ---------------- MMA flash attention -> padded [b][16][52][50] ----------------
__global__ __launch_bounds__(256) void attn_mma(const float* __restrict__ q,
                                                const float* __restrict__ kv,
                                                float* __restrict__ pad2) {
    const int b = blockIdx.y;
    const int mtile = blockIdx.x;
    const int q0 = mtile * 128;
    const int tid = threadIdx.x;
    const int wid = tid >> 5;
    const int lane = tid & 31;
    const int g = lane >> 2;
    const int t = lane & 3;

    __shared__ float k_s[16 * 136];
    __shared__ float v_s[128 * 24];

    uint32_t qa[2][4];
    #pragma unroll
    for (int kd = 0; kd < 2; ++kd)
        #pragma unroll
        for (int j = 0; j < 4; ++j) {
            int row = wid * 16 + g + (j & 1) * 8;
            int d = kd * 8 + t + (j >> 1) * 4;
            float v = q[((long)b * 16 + d) * SP + q0 + row] * 0.25f;
            qa[kd][j] = to_tf32(v);
        }

    float m[2] = { -3.4e38f, -3.4e38f };
    float l[2] = { 0.f, 0.f };
    float acc_o[2][4];
    #pragma unroll
    for (int dn = 0; dn < 2; ++dn)
        #pragma unroll
        for (int j = 0; j < 4; ++j) acc_o[dn][j] = 0.f;

    const long kvb = (long)b * 32 * SP;
    for (int kb = 0; kb < 18; ++kb) {
        __syncthreads();
        const int key0 = kb * 128;
        #pragma unroll
        for (int it = 0; it < 8; ++it) {
            int idx = it * 256 + tid;
            int c = idx >> 7;
            int key = idx & 127;
            k_s[c * 136 + key] =
                __uint_as_float(to_tf32(kv[kvb + (long)c * SP + key0 + key]));
        }
        #pragma unroll
        for (int it = 0; it < 8; ++it) {
            int idx = it * 256 + tid;
            int d = idx >> 7;
            int key = idx & 127;
            int kp = key & 7;
            int kap = (kp & 1) ? (kp >> 1) + 4 : (kp >> 1);
            int slot = (key & ~7) | kap;
            v_s[slot * 24 + d] =
                __uint_as_float(to_tf32(kv[kvb + (long)(16 + d) * SP + key0 + key]));
        }
        __syncthreads();

        float s_fr[16][4];
        #pragma unroll
        for (int nt = 0; nt < 16; ++nt) {
            float c4[4] = { 0.f, 0.f, 0.f, 0.f };
            #pragma unroll
            for (int kd = 0; kd < 2; ++kd) {
                uint32_t bfr[2];
                bfr[0] = __float_as_uint(k_s[(kd * 8 + t) * 136 + nt * 8 + g]);
                bfr[1] = __float_as_uint(k_s[(kd * 8 + t + 4) * 136 + nt * 8 + g]);
                mma_tf32(c4, qa[kd], bfr);
            }
            s_fr[nt][0] = c4[0]; s_fr[nt][1] = c4[1];
            s_fr[nt][2] = c4[2]; s_fr[nt][3] = c4[3];
        }

        #pragma unroll
        for (int r = 0; r < 2; ++r) {
            float vm = -3.4e38f;
            #pragma unroll
            for (int nt = 0; nt < 16; ++nt)
                vm = fmaxf(vm, fmaxf(s_fr[nt][r * 2], s_fr[nt][r * 2 + 1]));
            vm = fmaxf(vm, __shfl_xor_sync(0xffffffffu, vm, 1));
            vm = fmaxf(vm, __shfl_xor_sync(0xffffffffu, vm, 2));
            float mn = fmaxf(m[r], vm);
            float corr = __expf(m[r] - mn);
            m[r] = mn;
            float ls = 0.f;
            #pragma unroll
            for (int nt = 0; nt < 16; ++nt) {
                float e0 = __expf(s_fr[nt][r * 2] - mn);
                float e1 = __expf(s_fr[nt][r * 2 + 1] - mn);
                s_fr[nt][r * 2] = e0;
                s_fr[nt][r * 2 + 1] = e1;
                ls += e0 + e1;
            }
            ls += __shfl_xor_sync(0xffffffffu, ls, 1);
            ls += __shfl_xor_sync(0xffffffffu, ls, 2);
            l[r] = l[r] * corr + ls;
            #pragma unroll
            for (int dn = 0; dn < 2; ++dn) {
                acc_o[dn][r * 2] *= corr;
                acc_o[dn][r * 2 + 1] *= corr;
            }
        }

        #pragma unroll
        for (int nt = 0; nt < 16; ++nt) {
            uint32_t pa[4];
            pa[0] = __float_as_uint(s_fr[nt][0]);
            pa[1] = __float_as_uint(s_fr[nt][2]);
            pa[2] = __float_as_uint(s_fr[nt][1]);
            pa[3] = __float_as_uint(s_fr[nt][3]);
            #pragma unroll
            for (int dn = 0; dn < 2; ++dn) {
                uint32_t bfr[2];
                bfr[0] = __float_as_uint(v_s[(nt * 8 + t) * 24 + dn * 8 + g]);
                bfr[1] = __float_as_uint(v_s[(nt * 8 + t + 4) * 24 + dn * 8 + g]);
                mma_tf32(acc_o[dn], pa, bfr);
            }
        }
    }

    #pragma unroll
    for (int r = 0; r < 2; ++r) {
        float inv = 1.f / l[r];
        int pos = q0 + wid * 16 + g + r * 8;
        int py = pos / 48, px = pos - py * 48;
        #pragma unroll
        for (int dn = 0; dn < 2; ++dn)
            #pragma unroll
            for (int cc2 = 0; cc2 < 2; ++cc2) {
                int d = dn * 8 + 2 * t + cc2;
                pad2[((size_t)b * 16 + d) * 2600 + (py + 1) * 50 + (px + 1)] =
                    acc_o[dn][r * 2 + cc2] * inv;
            }
    }
}

// ---------------- launcher ----------------
extern "C" void kernel_launch(void* const* d_in, const int* in_sizes, int n_in,
                              void* d_out, int out_size) {
    const float* x       = (const float*)d_in[0];
    const float* xe      = (const float*)d_in[1];
    const float* temb    = (const float*)d_in[2];
    const float* gn1_w   = (const float*)d_in[3];
    const float* gn1_b   = (const float*)d_in[4];
    const float* conv1_w = (const float*)d_in[5];
    const float* conv1_b = (const float*)d_in[6];
    const float* aff_w   = (const float*)d_in[7];
    const float* aff_b   = (const float*)d_in[8];
    const float* gn2_w   = (const float*)d_in[9];
    const float* gn2_b   = (const float*)d_in[10];
    const float* conv2_w = (const float*)d_in[11];
    const float* conv2_b = (const float*)d_in[12];
    const float* q_w     = (const float*)d_in[13];
    const float* kv_w    = (const float*)d_in[14];
    const float* out_w   = (const float*)d_in[15];
    const float* out_b   = (const float*)d_in[16];

    float *padp, *pad2p, *wtp, *wtBp, *wt2p, *h, *xres, *qb, *kvb, *mean, *rstd, *gbsum;
    cudaGetSymbolAddress((void**)&padp,  g_pad);
    cudaGetSymbolAddress((void**)&pad2p, g_pad2);
    cudaGetSymbolAddress((void**)&wtp,   g_wt);
    cudaGetSymbolAddress((void**)&wtBp,  g_wtB);
    cudaGetSymbolAddress((void**)&wt2p,  g_wt2);
    cudaGetSymbolAddress((void**)&h,     g_h);
    cudaGetSymbolAddress((void**)&xres,  g_xres);
    cudaGetSymbolAddress((void**)&qb,    g_q);
    cudaGetSymbolAddress((void**)&kvb,   g_kv);
    cudaGetSymbolAddress((void**)&mean,  g_mean);
    cudaGetSymbolAddress((void**)&rstd,  g_rstd);
    cudaGetSymbolAddress((void**)&gbsum, g_gbsum);

    const int DSM_C = (4 * WBUFSZ + 2 * IBUFSZ) * 4;   // 84992 bytes
    const int DSM_16 = 4 * STG * 4;                    // 176128 bytes
    cudaFuncSetAttribute(conv_mma<0>, cudaFuncAttributeMaxDynamicSharedMemorySize, DSM_C);
    cudaFuncSetAttribute(conv_mma<1>, cudaFuncAttributeMaxDynamicSharedMemorySize, DSM_C);
    cudaFuncSetAttribute(conv_mma16, cudaFuncAttributeMaxDynamicSharedMemorySize, DSM_16);

    // launch 1: prep (affine + all weight transposes)
    prep_kernel<<<2700, 256>>>(temb, aff_w, aff_b, gbsum,
                               conv1_w, conv2_w, out_w, wtp, wtBp, wt2p);
    // 2, 3
    gn_stats<<<BB * 32, 256>>>(x, mean, rstd);
    gn_apply_pad<<<TOTAL / 256, 256>>>(x, mean, rstd, gn1_w, gn1_b, padp);
    // 4: conv_mma<0>  (profiled slot)
    conv_mma<0><<<dim3(18, BB), 256, DSM_C>>>(padp, wtp, conv1_b, gbsum, h);

    gn_stats<<<BB * 32, 256>>>(h, mean, rstd);
    gn_apply_pad<<<TOTAL / 256, 256>>>(h, mean, rstd, gn2_w, gn2_b, padp);
    conv_mma<1><<<dim3(18, BB), 256, DSM_C>>>(padp, wtBp, conv2_b, x, xres);

    conv1x1<16><<<dim3(9, BB), 256>>>(xres, q_w, qb);
    conv1x1<32><<<dim3(9, BB), 256>>>(xe, kv_w, kvb);
    attn_mma<<<dim3(18, BB), 256>>>(qb, kvb, pad2p);
    conv_mma16<<<dim3(18, BB), 256, DSM_16>>>(pad2p, wt2p, out_b, xres, (float*)d_out);
}